// round 10
// baseline (speedup 1.0000x reference)
#include <cuda_runtime.h>
#include <cuda_bf16.h>
#include <math.h>
#include <stdint.h>

// Problem dims
#define BB   64
#define SS   512
#define DD   768
#define WW   256
#define HH   384
#define FOURH 1536
#define CC   425
#define K2H  768
#define MM   (BB*SS)      // 32768 rows

// Recurrence config
#define NCD   64          // CTAs per direction (128 total)
#define CH    6           // h-indices per CTA (64*6 = 384)
#define RR    24          // gate rows per CTA (4 gates * CH)
#define RTH   384         // 12 warps: 4 m-tiles x 3 n-tiles

// -------- scratch (device globals; no allocation allowed) --------
__device__ __nv_bfloat16 g_xhi[MM * DD];
__device__ __nv_bfloat16 g_xlo[MM * DD];
__device__ float g_xpf[MM * FOURH];
__device__ float g_xpb[MM * FOURH];
__device__ __nv_bfloat16 g_f1hi[MM * K2H];
__device__ __nv_bfloat16 g_f1lo[MM * K2H];
__device__ __nv_bfloat16 g_hbhi[2][2][BB * HH];   // [dir][parity][b*384+k]
__device__ __nv_bfloat16 g_hblo[2][2][BB * HH];
__device__ unsigned g_bar[2][SS][8];              // split barrier counters
__device__ __nv_bfloat16 g_wihf_hi[FOURH * DD], g_wihf_lo[FOURH * DD];
__device__ __nv_bfloat16 g_wihb_hi[FOURH * DD], g_wihb_lo[FOURH * DD];
__device__ __nv_bfloat16 g_wlin_hi[CC * K2H],  g_wlin_lo[CC * K2H];

// ---------------- small helpers ----------------
__device__ __forceinline__ uint32_t smem_u32(const void* p) {
    uint32_t a;
    asm("{ .reg .u64 t; cvta.to.shared.u64 t, %1; cvt.u32.u64 %0, t; }"
        : "=r"(a) : "l"(p));
    return a;
}
__device__ __forceinline__ void cp16(uint32_t d, const void* s, bool v) {
    int sz = v ? 16 : 0;
    asm volatile("cp.async.cg.shared.global [%0], [%1], 16, %2;\n"
                 :: "r"(d), "l"(s), "r"(sz));
}
#define CP_COMMIT() asm volatile("cp.async.commit_group;\n")
#define CP_WAIT(n)  asm volatile("cp.async.wait_group %0;\n" :: "n"(n))

#define LDM4(r, addr) \
    asm volatile("ldmatrix.sync.aligned.m8n8.x4.shared.b16 {%0,%1,%2,%3}, [%4];" \
        : "=r"((r)[0]), "=r"((r)[1]), "=r"((r)[2]), "=r"((r)[3]) : "r"(addr))

#define MMA(d, a, b0, b1) \
    asm volatile("mma.sync.aligned.m16n8k16.row.col.f32.bf16.bf16.f32 " \
        "{%0,%1,%2,%3},{%4,%5,%6,%7},{%8,%9},{%0,%1,%2,%3};" \
        : "+f"((d)[0]), "+f"((d)[1]), "+f"((d)[2]), "+f"((d)[3]) \
        : "r"((a)[0]), "r"((a)[1]), "r"((a)[2]), "r"((a)[3]), "r"(b0), "r"(b1))

// fast activations (clamped; rel err ~1e-6)
__device__ __forceinline__ float sigf(float x) {
    x = fminf(fmaxf(x, -30.0f), 30.0f);
    return __fdividef(1.0f, 1.0f + __expf(-x));
}
__device__ __forceinline__ float tanhfast(float x) {
    x = fminf(fmaxf(x, -15.0f), 15.0f);
    float e = __expf(2.0f * x);
    return __fdividef(e - 1.0f, e + 1.0f);
}

// ---------------- fused init (h state, barriers) + weight hi/lo split ------
__global__ void initcvt_kernel(const float* __restrict__ in0, __nv_bfloat16* __restrict__ hi0,
                               __nv_bfloat16* __restrict__ lo0, int n0,
                               const float* __restrict__ in1, __nv_bfloat16* __restrict__ hi1,
                               __nv_bfloat16* __restrict__ lo1, int n1,
                               const float* __restrict__ in2, __nv_bfloat16* __restrict__ hi2,
                               __nv_bfloat16* __restrict__ lo2, int n2)
{
    int gid = blockIdx.x * blockDim.x + threadIdx.x;

    // init part (low indices only)
    if (gid < 2 * BB * HH) {
        g_hbhi[gid / (BB * HH)][0][gid % (BB * HH)] = __float2bfloat16(0.0f);
        g_hblo[gid / (BB * HH)][0][gid % (BB * HH)] = __float2bfloat16(0.0f);
    }
    if (gid < 2 * SS * 8) (&g_bar[0][0][0])[gid] = 0u;

    // cvt part
    int i = gid;
    const float* in; __nv_bfloat16 *hi, *lo;
    if (i < n0)                { in = in0; hi = hi0; lo = lo0; }
    else if (i < n0 + n1)      { i -= n0; in = in1; hi = hi1; lo = lo1; }
    else if (i < n0 + n1 + n2) { i -= n0 + n1; in = in2; hi = hi2; lo = lo2; }
    else return;
    float v = in[i];
    __nv_bfloat16 h = __float2bfloat16(v);
    hi[i] = h;
    lo[i] = __float2bfloat16(v - __bfloat162float(h));
}

// ---------------- segment mean pool (writes split bf16) ----------------
__global__ void pool_kernel(const float* __restrict__ f0,
                            const int*   __restrict__ counts,
                            __nv_bfloat16* __restrict__ xhi,
                            __nv_bfloat16* __restrict__ xlo)
{
    __shared__ int s_start[WW];
    __shared__ int s_cnt[WW];
    int b = blockIdx.x;
    int tid = threadIdx.x;
    if (tid == 0) {
        int run = 0;
        for (int j = 0; j < WW; ++j) {
            int c = counts[b * WW + j];
            s_start[j] = run; s_cnt[j] = c; run += c;
        }
    }
    __syncthreads();
    const float* fb = f0 + (size_t)b * SS * DD;
    __nv_bfloat16* xh = xhi + (size_t)b * SS * DD;
    __nv_bfloat16* xl = xlo + (size_t)b * SS * DD;
    for (int idx = tid; idx < WW * DD; idx += blockDim.x) {
        int j = idx / DD, d = idx - j * DD;
        int st = s_start[j], c = s_cnt[j];
        float v = 0.0f;
        for (int p = 0; p < c; ++p) v += fb[(size_t)(st + p) * DD + d];
        v /= (float)c;
        __nv_bfloat16 h = __float2bfloat16(v);
        xh[idx] = h;
        xl[idx] = __float2bfloat16(v - __bfloat162float(h));
    }
    for (int idx = tid; idx < (SS - WW) * DD; idx += blockDim.x) {
        float v = fb[WW * DD + idx];
        __nv_bfloat16 h = __float2bfloat16(v);
        xh[WW * DD + idx] = h;
        xl[WW * DD + idx] = __float2bfloat16(v - __bfloat162float(h));
    }
}

// ---------------- split-bf16 tensor-core GEMM (mma.sync) ----------------
// 512 threads / CTA, 16 warps, 32x32 warp tiles on a 128x128 block tile.
// blockIdx.z selects job {B-set, biases, C} (both proj GEMMs in one launch).
#define ARRB  (128 * 80)
#define STGB  (4 * ARRB)

__global__ void __launch_bounds__(512, 1)
gemm3_kernel(const __nv_bfloat16* __restrict__ Ahi, const __nv_bfloat16* __restrict__ Alo,
             const __nv_bfloat16* __restrict__ Bh0, const __nv_bfloat16* __restrict__ Bl0,
             const float* __restrict__ b1_0, const float* __restrict__ b2_0,
             float* __restrict__ C0,
             const __nv_bfloat16* __restrict__ Bh1, const __nv_bfloat16* __restrict__ Bl1,
             const float* __restrict__ b1_1, const float* __restrict__ b2_1,
             float* __restrict__ C1,
             int N, int K)
{
    extern __shared__ char smem[];
    uint32_t sb = smem_u32(smem);
    int tid = threadIdx.x, lane = tid & 31, wid = tid >> 5;
    int wm = wid >> 2, wn = wid & 3;          // 4x4 warp grid, 32x32 tiles
    int bm = blockIdx.y, bn = blockIdx.x;

    const __nv_bfloat16* Bhi = blockIdx.z ? Bh1 : Bh0;
    const __nv_bfloat16* Blo = blockIdx.z ? Bl1 : Bl0;
    const float* bias1 = blockIdx.z ? b1_1 : b1_0;
    const float* bias2 = blockIdx.z ? b2_1 : b2_0;
    float* C = blockIdx.z ? C1 : C0;

    // load mapping: 4 threads per row, 1x16B chunk each per array
    int lr = tid >> 2;                 // 0..127
    int lc = tid & 3;                  // 0..3
    int arow = bm * 128 + lr;
    int brow = bn * 128 + lr;
    bool bv  = brow < N;
    const __nv_bfloat16* pAh = Ahi + (size_t)arow * K;
    const __nv_bfloat16* pAl = Alo + (size_t)arow * K;
    const __nv_bfloat16* pBh = Bhi + (size_t)(bv ? brow : 0) * K;
    const __nv_bfloat16* pBl = Blo + (size_t)(bv ? brow : 0) * K;
    uint32_t sd = sb + lr * 80 + lc * 16;

    float acc[2][4][4];
#pragma unroll
    for (int a = 0; a < 2; ++a)
#pragma unroll
        for (int b = 0; b < 4; ++b)
#pragma unroll
            for (int c = 0; c < 4; ++c) acc[a][b][c] = 0.0f;

    int KT = K >> 5;

    // prologue: stage 0
    cp16(sd + 0 * ARRB, pAh + lc * 8, true);
    cp16(sd + 1 * ARRB, pAl + lc * 8, true);
    cp16(sd + 2 * ARRB, pBh + lc * 8, bv);
    cp16(sd + 3 * ARRB, pBl + lc * 8, bv);
    CP_COMMIT();

    int la  = lane & 15, lc4 = lane >> 4;
    int lb  = (lane & 7) + ((lane & 16) >> 1);
    int lbc = (lane >> 3) & 1;

    for (int i = 0; i < KT; ++i) {
        CP_WAIT(0);
        __syncthreads();
        if (i + 1 < KT) {
            int ko = (i + 1) << 5;
            uint32_t d = sd + ((i + 1) & 1) * STGB;
            cp16(d + 0 * ARRB, pAh + ko + lc * 8, true);
            cp16(d + 1 * ARRB, pAl + ko + lc * 8, true);
            cp16(d + 2 * ARRB, pBh + ko + lc * 8, bv);
            cp16(d + 3 * ARRB, pBl + ko + lc * 8, bv);
            CP_COMMIT();
        }
        uint32_t st = sb + (i & 1) * STGB;
#pragma unroll
        for (int kh = 0; kh < 2; ++kh) {
            uint32_t aaddr = st + (wm * 32 + la) * 80 + (kh * 2 + lc4) * 16;
            uint32_t ah[2][4], al[2][4];
#pragma unroll
            for (int mt = 0; mt < 2; ++mt) {
                LDM4(ah[mt], aaddr + mt * 1280);
                LDM4(al[mt], aaddr + mt * 1280 + ARRB);
            }
            uint32_t bbase = st + 2 * ARRB + (wn * 32 + lb) * 80 + (kh * 2 + lbc) * 16;
            uint32_t bh[2][4], bl[2][4];
#pragma unroll
            for (int ntp = 0; ntp < 2; ++ntp) {
                LDM4(bh[ntp], bbase + ntp * 1280);
                LDM4(bl[ntp], bbase + ntp * 1280 + ARRB);
            }
            // term 1: Ah*Bh
#pragma unroll
            for (int mt = 0; mt < 2; ++mt)
#pragma unroll
                for (int ntp = 0; ntp < 2; ++ntp) {
                    MMA(acc[mt][2 * ntp + 0], ah[mt], bh[ntp][0], bh[ntp][1]);
                    MMA(acc[mt][2 * ntp + 1], ah[mt], bh[ntp][2], bh[ntp][3]);
                }
            // term 2: Ah*Bl
#pragma unroll
            for (int mt = 0; mt < 2; ++mt)
#pragma unroll
                for (int ntp = 0; ntp < 2; ++ntp) {
                    MMA(acc[mt][2 * ntp + 0], ah[mt], bl[ntp][0], bl[ntp][1]);
                    MMA(acc[mt][2 * ntp + 1], ah[mt], bl[ntp][2], bl[ntp][3]);
                }
            // term 3: Al*Bh
#pragma unroll
            for (int mt = 0; mt < 2; ++mt)
#pragma unroll
                for (int ntp = 0; ntp < 2; ++ntp) {
                    MMA(acc[mt][2 * ntp + 0], al[mt], bh[ntp][0], bh[ntp][1]);
                    MMA(acc[mt][2 * ntp + 1], al[mt], bh[ntp][2], bh[ntp][3]);
                }
        }
        __syncthreads();
    }

    // epilogue
#pragma unroll
    for (int mt = 0; mt < 2; ++mt) {
        int m0 = bm * 128 + wm * 32 + mt * 16 + (lane >> 2);
#pragma unroll
        for (int nt = 0; nt < 4; ++nt) {
            int n0 = bn * 128 + wn * 32 + nt * 8 + (lane & 3) * 2;
            float* a = acc[mt][nt];
            if (n0 < N) {
                float bs = bias1[n0] + (bias2 ? bias2[n0] : 0.0f);
                C[(size_t)m0 * N + n0]       = a[0] + bs;
                C[(size_t)(m0 + 8) * N + n0] = a[2] + bs;
            }
            if (n0 + 1 < N) {
                float bs = bias1[n0 + 1] + (bias2 ? bias2[n0 + 1] : 0.0f);
                C[(size_t)m0 * N + n0 + 1]       = a[1] + bs;
                C[(size_t)(m0 + 8) * N + n0 + 1] = a[3] + bs;
            }
        }
    }
}

// ---------------- persistent tensor-core LSTM recurrence ----------------
#define LA_HI   0
#define LA_LO   50176           // 64 rows * 784B pitch
#define LW_HI   100352
#define LW_LO   119168          // 24 rows * 784B
#define LGATES  137984          // 64 * 26 floats
#define LCS     144640          // 384 floats
#define LSMEM   146176
#define PITCH   784

__global__ void __launch_bounds__(RTH, 1)
lstm_kernel(const float* __restrict__ Whh_f, const float* __restrict__ Whh_b)
{
    extern __shared__ char smem[];
    uint32_t sb = smem_u32(smem);
    float* gates_s = (float*)(smem + LGATES);
    float* c_s     = (float*)(smem + LCS);

    int cta = blockIdx.x;
    int dir = (cta >= NCD) ? 1 : 0;
    int ci  = cta - dir * NCD;
    const float* Whh = dir ? Whh_b : Whh_f;
    const float* xp  = dir ? g_xpb : g_xpf;
    int n0  = ci * CH;
    int tid = threadIdx.x;
    int lane = tid & 31, wid = tid >> 5;
    int mt = wid & 3;          // m-tile (16 b rows)
    int nt = wid >> 2;         // n-tile (8 gate rows)

    // ---- load + split Whh slice into SMEM (once) ----
    for (int idx = tid; idx < RR * HH; idx += RTH) {
        int r = idx / HH, k = idx - r * HH;
        int gi = r / CH, j = r - gi * CH;
        float v = Whh[(size_t)(gi * HH + n0 + j) * HH + k];
        __nv_bfloat16 h = __float2bfloat16(v);
        *(__nv_bfloat16*)(smem + LW_HI + r * PITCH + k * 2) = h;
        *(__nv_bfloat16*)(smem + LW_LO + r * PITCH + k * 2) =
            __float2bfloat16(v - __bfloat162float(h));
    }
    for (int idx = tid; idx < CH * BB; idx += RTH) c_s[idx] = 0.0f;
    __syncthreads();

    int cj = tid >> 6;         // 0..5
    int cb = tid & 63;

    int la  = lane & 15, lc4 = lane >> 4;
    uint32_t aAddrBase = sb + LA_HI + (mt * 16 + la) * PITCH + lc4 * 16;
    uint32_t bAddrBase = sb + LW_HI + ((lane >= 16) ? (LW_LO - LW_HI) : 0u)
                       + (nt * 8 + (lane & 7)) * PITCH + ((lane >> 3) & 1) * 16;

    float xg[4];
    {
        int t0 = dir ? (SS - 1) : 0;
        const float* xr = &xp[((size_t)cb * SS + t0) * FOURH + n0 + cj];
#pragma unroll
        for (int gi = 0; gi < 4; ++gi) xg[gi] = __ldg(xr + gi * HH);
    }

    for (int s = 0; s < SS; ++s) {
        int t = dir ? (SS - 1 - s) : s;
        int p = s & 1;

        const char* srcH = (const char*)&g_hbhi[dir][p][0];
        const char* srcL = (const char*)&g_hblo[dir][p][0];
#pragma unroll
        for (int q = 0; q < 4; ++q) {
#pragma unroll
            for (int i = 0; i < 2; ++i) {
                int e = i * RTH + tid;            // 0..767
                int row = e / 12, cc = e - row * 12;
                uint32_t so = row * 768 + q * 192 + cc * 16;
                uint32_t doff = row * PITCH + q * 192 + cc * 16;
                cp16(sb + LA_HI + doff, srcH + so, true);
                cp16(sb + LA_LO + doff, srcL + so, true);
            }
            CP_COMMIT();
        }

        float acc[4] = {0.f, 0.f, 0.f, 0.f};
#pragma unroll
        for (int q = 0; q < 4; ++q) {
            if      (q == 0) CP_WAIT(3);
            else if (q == 1) CP_WAIT(2);
            else if (q == 2) CP_WAIT(1);
            else             CP_WAIT(0);
            __syncthreads();
#pragma unroll
            for (int kk = 0; kk < 6; ++kk) {
                int k16 = q * 6 + kk;
                uint32_t ka = aAddrBase + k16 * 32;
                uint32_t kb = bAddrBase + k16 * 32;
                uint32_t ah[4], al[4], bb[4];
                LDM4(ah, ka);
                LDM4(al, ka + (LA_LO - LA_HI));
                LDM4(bb, kb);                      // bb = {bh0, bh1, bl0, bl1}
                MMA(acc, ah, bb[0], bb[1]);
                MMA(acc, ah, bb[2], bb[3]);
                MMA(acc, al, bb[0], bb[1]);
            }
        }

        {
            int brow = mt * 16 + (lane >> 2);
            int rcol = nt * 8 + (lane & 3) * 2;
            *(float2*)&gates_s[brow * 26 + rcol]       = make_float2(acc[0], acc[1]);
            *(float2*)&gates_s[(brow + 8) * 26 + rcol] = make_float2(acc[2], acc[3]);
        }
        __syncthreads();

        {
            float ig = gates_s[cb * 26 + 0 * CH + cj] + xg[0];
            float fg = gates_s[cb * 26 + 1 * CH + cj] + xg[1];
            float gg = gates_s[cb * 26 + 2 * CH + cj] + xg[2];
            float og = gates_s[cb * 26 + 3 * CH + cj] + xg[3];
            float c  = c_s[tid];
            c = sigf(fg) * c + sigf(ig) * tanhfast(gg);
            float h = sigf(og) * tanhfast(c);
            c_s[tid] = c;
            __nv_bfloat16 hh = __float2bfloat16(h);
            __nv_bfloat16 hl = __float2bfloat16(h - __bfloat162float(hh));
            int np = (s + 1) & 1;
            g_hbhi[dir][np][cb * HH + n0 + cj] = hh;
            g_hblo[dir][np][cb * HH + n0 + cj] = hl;
            size_t fo = ((size_t)cb * SS + t) * K2H + dir * HH + n0 + cj;
            g_f1hi[fo] = hh;
            g_f1lo[fo] = hl;
        }

        if (s + 1 < SS) {
            int t1 = dir ? (SS - 2 - s) : (s + 1);
            const float* xr = &xp[((size_t)cb * SS + t1) * FOURH + n0 + cj];
#pragma unroll
            for (int gi = 0; gi < 4; ++gi) xg[gi] = __ldg(xr + gi * HH);
        }

        __threadfence();
        __syncthreads();
        if (tid == 0) {
            atomicAdd(&g_bar[dir][s][ci & 7], 1u);
            const volatile unsigned* bw = &g_bar[dir][s][0];
            unsigned sum;
            do {
                sum = bw[0] + bw[1] + bw[2] + bw[3] + bw[4] + bw[5] + bw[6] + bw[7];
            } while (sum < (unsigned)NCD);
        }
        __syncthreads();
    }
}

// ---------------- launcher ----------------
extern "C" void kernel_launch(void* const* d_in, const int* in_sizes, int n_in,
                              void* d_out, int out_size)
{
    const float* f0     = (const float*)d_in[0];
    const int*   counts = (const int*)  d_in[1];
    const float* Wih_f  = (const float*)d_in[2];
    const float* Whh_f  = (const float*)d_in[3];
    const float* bih_f  = (const float*)d_in[4];
    const float* bhh_f  = (const float*)d_in[5];
    const float* Wih_b  = (const float*)d_in[6];
    const float* Whh_b  = (const float*)d_in[7];
    const float* bih_b  = (const float*)d_in[8];
    const float* bhh_b  = (const float*)d_in[9];
    const float* Wlin   = (const float*)d_in[10];
    const float* blin   = (const float*)d_in[11];
    float* out = (float*)d_out;

    void* p;
    cudaGetSymbolAddress(&p, g_xhi);     __nv_bfloat16* xhi = (__nv_bfloat16*)p;
    cudaGetSymbolAddress(&p, g_xlo);     __nv_bfloat16* xlo = (__nv_bfloat16*)p;
    cudaGetSymbolAddress(&p, g_xpf);     float* gxpf = (float*)p;
    cudaGetSymbolAddress(&p, g_xpb);     float* gxpb = (float*)p;
    cudaGetSymbolAddress(&p, g_f1hi);    __nv_bfloat16* f1hi = (__nv_bfloat16*)p;
    cudaGetSymbolAddress(&p, g_f1lo);    __nv_bfloat16* f1lo = (__nv_bfloat16*)p;
    cudaGetSymbolAddress(&p, g_wihf_hi); __nv_bfloat16* wfh = (__nv_bfloat16*)p;
    cudaGetSymbolAddress(&p, g_wihf_lo); __nv_bfloat16* wfl = (__nv_bfloat16*)p;
    cudaGetSymbolAddress(&p, g_wihb_hi); __nv_bfloat16* wbh = (__nv_bfloat16*)p;
    cudaGetSymbolAddress(&p, g_wihb_lo); __nv_bfloat16* wbl = (__nv_bfloat16*)p;
    cudaGetSymbolAddress(&p, g_wlin_hi); __nv_bfloat16* wlh = (__nv_bfloat16*)p;
    cudaGetSymbolAddress(&p, g_wlin_lo); __nv_bfloat16* wll = (__nv_bfloat16*)p;

    cudaFuncSetAttribute(lstm_kernel, cudaFuncAttributeMaxDynamicSharedMemorySize, LSMEM);
    cudaFuncSetAttribute(gemm3_kernel, cudaFuncAttributeMaxDynamicSharedMemorySize, 2 * STGB);

    int nw = FOURH * DD;
    int nl = CC * K2H;
    int ncvt = 2 * nw + nl;
    // launch 0: init + weight split
    initcvt_kernel<<<(ncvt + 255) / 256, 256>>>(Wih_f, wfh, wfl, nw,
                                                Wih_b, wbh, wbl, nw,
                                                Wlin,  wlh, wll, nl);
    // launch 1: pool
    pool_kernel<<<BB, 256>>>(f0, counts, xhi, xlo);

    // launch 2: BOTH projection GEMMs (blockIdx.z selects job)
    dim3 gproj(FOURH / 128, MM / 128, 2);   // 12 x 256 x 2
    gemm3_kernel<<<gproj, 512, 2 * STGB>>>(xhi, xlo,
                                           wfh, wfl, bih_f, bhh_f, gxpf,
                                           wbh, wbl, bih_b, bhh_b, gxpb,
                                           FOURH, DD);

    // launch 3: LSTM (ncu captures this index)
    lstm_kernel<<<2 * NCD, RTH, LSMEM>>>(Whh_f, Whh_b);

    // launch 4: output linear
    dim3 gout((CC + 127) / 128, MM / 128, 1);
    gemm3_kernel<<<gout, 512, 2 * STGB>>>(f1hi, f1lo,
                                          wlh, wll, blin, nullptr, out,
                                          wlh, wll, blin, nullptr, out,
                                          CC, K2H);
}

// round 11
// speedup vs baseline: 1.5009x; 1.5009x over previous
#include <cuda_runtime.h>
#include <cuda_bf16.h>
#include <math.h>
#include <stdint.h>

// Problem dims
#define BB   64
#define SS   512
#define DD   768
#define WW   256
#define HH   384
#define FOURH 1536
#define CC   425
#define K2H  768
#define MM   (BB*SS)      // 32768 rows

// Recurrence config
#define NCD   64          // CTAs per direction (128 total)
#define CH    6           // h-indices per CTA (64*6 = 384)
#define RR    24          // gate rows per CTA (4 gates * CH)
#define RTH   384         // 12 warps: 4 m-tiles x 3 n-tiles

// -------- scratch (device globals; no allocation allowed) --------
__device__ __nv_bfloat16 g_xhi[MM * DD];
__device__ __nv_bfloat16 g_xlo[MM * DD];
__device__ float g_xptf[MM * FOURH];              // proj fwd, layout [t][feat][b]
__device__ float g_xptb[MM * FOURH];              // proj bwd, layout [t][feat][b]
__device__ __nv_bfloat16 g_f1thi[MM * K2H];       // [t][feat][b]
__device__ __nv_bfloat16 g_f1tlo[MM * K2H];
__device__ __nv_bfloat16 g_f1hi[MM * K2H];        // [b][t][feat] (post-transpose)
__device__ __nv_bfloat16 g_f1lo[MM * K2H];
__device__ __nv_bfloat16 g_hbhi[2][2][BB * HH];   // [dir][parity][b*384+k]
__device__ __nv_bfloat16 g_hblo[2][2][BB * HH];
__device__ unsigned g_bar[2][SS][8];              // split barrier counters
__device__ __nv_bfloat16 g_wihf_hi[FOURH * DD], g_wihf_lo[FOURH * DD];
__device__ __nv_bfloat16 g_wihb_hi[FOURH * DD], g_wihb_lo[FOURH * DD];
__device__ __nv_bfloat16 g_wlin_hi[CC * K2H],  g_wlin_lo[CC * K2H];

// ---------------- small helpers ----------------
__device__ __forceinline__ uint32_t smem_u32(const void* p) {
    uint32_t a;
    asm("{ .reg .u64 t; cvta.to.shared.u64 t, %1; cvt.u32.u64 %0, t; }"
        : "=r"(a) : "l"(p));
    return a;
}
__device__ __forceinline__ void cp16(uint32_t d, const void* s, bool v) {
    int sz = v ? 16 : 0;
    asm volatile("cp.async.cg.shared.global [%0], [%1], 16, %2;\n"
                 :: "r"(d), "l"(s), "r"(sz));
}
#define CP_COMMIT() asm volatile("cp.async.commit_group;\n")
#define CP_WAIT(n)  asm volatile("cp.async.wait_group %0;\n" :: "n"(n))

#define LDM4(r, addr) \
    asm volatile("ldmatrix.sync.aligned.m8n8.x4.shared.b16 {%0,%1,%2,%3}, [%4];" \
        : "=r"((r)[0]), "=r"((r)[1]), "=r"((r)[2]), "=r"((r)[3]) : "r"(addr))

#define MMA(d, a, b0, b1) \
    asm volatile("mma.sync.aligned.m16n8k16.row.col.f32.bf16.bf16.f32 " \
        "{%0,%1,%2,%3},{%4,%5,%6,%7},{%8,%9},{%0,%1,%2,%3};" \
        : "+f"((d)[0]), "+f"((d)[1]), "+f"((d)[2]), "+f"((d)[3]) \
        : "r"((a)[0]), "r"((a)[1]), "r"((a)[2]), "r"((a)[3]), "r"(b0), "r"(b1))

// fast activations (clamped; rel err ~1e-6)
__device__ __forceinline__ float sigf(float x) {
    x = fminf(fmaxf(x, -30.0f), 30.0f);
    return __fdividef(1.0f, 1.0f + __expf(-x));
}
__device__ __forceinline__ float tanhfast(float x) {
    x = fminf(fmaxf(x, -15.0f), 15.0f);
    float e = __expf(2.0f * x);
    return __fdividef(e - 1.0f, e + 1.0f);
}

// ---------------- fused init (h state, barriers) + weight hi/lo split ------
__global__ void initcvt_kernel(const float* __restrict__ in0, __nv_bfloat16* __restrict__ hi0,
                               __nv_bfloat16* __restrict__ lo0, int n0,
                               const float* __restrict__ in1, __nv_bfloat16* __restrict__ hi1,
                               __nv_bfloat16* __restrict__ lo1, int n1,
                               const float* __restrict__ in2, __nv_bfloat16* __restrict__ hi2,
                               __nv_bfloat16* __restrict__ lo2, int n2)
{
    int gid = blockIdx.x * blockDim.x + threadIdx.x;

    if (gid < 2 * BB * HH) {
        g_hbhi[gid / (BB * HH)][0][gid % (BB * HH)] = __float2bfloat16(0.0f);
        g_hblo[gid / (BB * HH)][0][gid % (BB * HH)] = __float2bfloat16(0.0f);
    }
    if (gid < 2 * SS * 8) (&g_bar[0][0][0])[gid] = 0u;

    int i = gid;
    const float* in; __nv_bfloat16 *hi, *lo;
    if (i < n0)                { in = in0; hi = hi0; lo = lo0; }
    else if (i < n0 + n1)      { i -= n0; in = in1; hi = hi1; lo = lo1; }
    else if (i < n0 + n1 + n2) { i -= n0 + n1; in = in2; hi = hi2; lo = lo2; }
    else return;
    float v = in[i];
    __nv_bfloat16 h = __float2bfloat16(v);
    hi[i] = h;
    lo[i] = __float2bfloat16(v - __bfloat162float(h));
}

// ---------------- segment mean pool (writes split bf16) ----------------
__global__ void pool_kernel(const float* __restrict__ f0,
                            const int*   __restrict__ counts,
                            __nv_bfloat16* __restrict__ xhi,
                            __nv_bfloat16* __restrict__ xlo)
{
    __shared__ int s_start[WW];
    __shared__ int s_cnt[WW];
    int b = blockIdx.x;
    int tid = threadIdx.x;
    if (tid == 0) {
        int run = 0;
        for (int j = 0; j < WW; ++j) {
            int c = counts[b * WW + j];
            s_start[j] = run; s_cnt[j] = c; run += c;
        }
    }
    __syncthreads();
    const float* fb = f0 + (size_t)b * SS * DD;
    __nv_bfloat16* xh = xhi + (size_t)b * SS * DD;
    __nv_bfloat16* xl = xlo + (size_t)b * SS * DD;
    for (int idx = tid; idx < WW * DD; idx += blockDim.x) {
        int j = idx / DD, d = idx - j * DD;
        int st = s_start[j], c = s_cnt[j];
        float v = 0.0f;
        for (int p = 0; p < c; ++p) v += fb[(size_t)(st + p) * DD + d];
        v /= (float)c;
        __nv_bfloat16 h = __float2bfloat16(v);
        xh[idx] = h;
        xl[idx] = __float2bfloat16(v - __bfloat162float(h));
    }
    for (int idx = tid; idx < (SS - WW) * DD; idx += blockDim.x) {
        float v = fb[WW * DD + idx];
        __nv_bfloat16 h = __float2bfloat16(v);
        xh[WW * DD + idx] = h;
        xl[WW * DD + idx] = __float2bfloat16(v - __bfloat162float(h));
    }
}

// ---------------- split-bf16 tensor-core GEMM (round-8 proven version) -----
// C = (Ahi+Alo)*(Bhi+Blo)^T + bias1 + bias2 ; 3 terms, fp32 accumulate.
// 128x128 tile, BK=32, 256 threads, 64x32 warp tiles.
// tstore=0: C[m][n] row-major. tstore=1: C[(t*N+n)*64 + b] with m=b*512+t.
#define ARRB  (128 * 80)
#define STGB  (4 * ARRB)

__global__ void __launch_bounds__(256, 1)
gemm3_kernel(const __nv_bfloat16* __restrict__ Ahi, const __nv_bfloat16* __restrict__ Alo,
             const __nv_bfloat16* __restrict__ Bhi, const __nv_bfloat16* __restrict__ Blo,
             const float* __restrict__ bias1, const float* __restrict__ bias2,
             float* __restrict__ C, int N, int K, int tstore)
{
    extern __shared__ char smem[];
    uint32_t sb = smem_u32(smem);
    int tid = threadIdx.x, lane = tid & 31, wid = tid >> 5;
    int wm = wid >> 2, wn = wid & 3;
    int bm = blockIdx.y, bn = blockIdx.x;

    int lr = tid >> 1;
    int lc = (tid & 1) * 2;
    int arow = bm * 128 + lr;
    int brow = bn * 128 + lr;
    bool bv  = brow < N;
    const __nv_bfloat16* pAh = Ahi + (size_t)arow * K;
    const __nv_bfloat16* pAl = Alo + (size_t)arow * K;
    const __nv_bfloat16* pBh = Bhi + (size_t)(bv ? brow : 0) * K;
    const __nv_bfloat16* pBl = Blo + (size_t)(bv ? brow : 0) * K;
    uint32_t sd = sb + lr * 80 + lc * 16;

    float acc[4][4][4];
#pragma unroll
    for (int a = 0; a < 4; ++a)
#pragma unroll
        for (int b = 0; b < 4; ++b)
#pragma unroll
            for (int c = 0; c < 4; ++c) acc[a][b][c] = 0.0f;

    int KT = K >> 5;

    {
        uint32_t d = sd;
#pragma unroll
        for (int cc = 0; cc < 2; ++cc) {
            cp16(d + cc * 16 + 0 * ARRB, pAh + (lc + cc) * 8, true);
            cp16(d + cc * 16 + 1 * ARRB, pAl + (lc + cc) * 8, true);
            cp16(d + cc * 16 + 2 * ARRB, pBh + (lc + cc) * 8, bv);
            cp16(d + cc * 16 + 3 * ARRB, pBl + (lc + cc) * 8, bv);
        }
        CP_COMMIT();
    }

    int la  = lane & 15, lc4 = lane >> 4;
    int lb  = (lane & 7) + ((lane & 16) >> 1);
    int lbc = (lane >> 3) & 1;

    for (int i = 0; i < KT; ++i) {
        CP_WAIT(0);
        __syncthreads();
        if (i + 1 < KT) {
            int ko = (i + 1) << 5;
            uint32_t d = sd + ((i + 1) & 1) * STGB;
#pragma unroll
            for (int cc = 0; cc < 2; ++cc) {
                cp16(d + cc * 16 + 0 * ARRB, pAh + ko + (lc + cc) * 8, true);
                cp16(d + cc * 16 + 1 * ARRB, pAl + ko + (lc + cc) * 8, true);
                cp16(d + cc * 16 + 2 * ARRB, pBh + ko + (lc + cc) * 8, bv);
                cp16(d + cc * 16 + 3 * ARRB, pBl + ko + (lc + cc) * 8, bv);
            }
            CP_COMMIT();
        }
        uint32_t st = sb + (i & 1) * STGB;
#pragma unroll
        for (int kh = 0; kh < 2; ++kh) {
            uint32_t aaddr = st + (wm * 64 + la) * 80 + (kh * 2 + lc4) * 16;
            uint32_t ah[4][4], al[4][4];
#pragma unroll
            for (int mt = 0; mt < 4; ++mt) {
                LDM4(ah[mt], aaddr + mt * 1280);
                LDM4(al[mt], aaddr + mt * 1280 + ARRB);
            }
            uint32_t bbase = st + 2 * ARRB + (wn * 32 + lb) * 80 + (kh * 2 + lbc) * 16;
            uint32_t bh[2][4], bl[2][4];
#pragma unroll
            for (int ntp = 0; ntp < 2; ++ntp) {
                LDM4(bh[ntp], bbase + ntp * 1280);
                LDM4(bl[ntp], bbase + ntp * 1280 + ARRB);
            }
#pragma unroll
            for (int mt = 0; mt < 4; ++mt)
#pragma unroll
                for (int ntp = 0; ntp < 2; ++ntp) {
                    MMA(acc[mt][2 * ntp + 0], ah[mt], bh[ntp][0], bh[ntp][1]);
                    MMA(acc[mt][2 * ntp + 1], ah[mt], bh[ntp][2], bh[ntp][3]);
                }
#pragma unroll
            for (int mt = 0; mt < 4; ++mt)
#pragma unroll
                for (int ntp = 0; ntp < 2; ++ntp) {
                    MMA(acc[mt][2 * ntp + 0], ah[mt], bl[ntp][0], bl[ntp][1]);
                    MMA(acc[mt][2 * ntp + 1], ah[mt], bl[ntp][2], bl[ntp][3]);
                }
#pragma unroll
            for (int mt = 0; mt < 4; ++mt)
#pragma unroll
                for (int ntp = 0; ntp < 2; ++ntp) {
                    MMA(acc[mt][2 * ntp + 0], al[mt], bh[ntp][0], bh[ntp][1]);
                    MMA(acc[mt][2 * ntp + 1], al[mt], bh[ntp][2], bh[ntp][3]);
                }
        }
        __syncthreads();
    }

    // epilogue
#pragma unroll
    for (int mt = 0; mt < 4; ++mt) {
        int m0 = bm * 128 + wm * 64 + mt * 16 + (lane >> 2);
#pragma unroll
        for (int nt = 0; nt < 4; ++nt) {
            int n0 = bn * 128 + wn * 32 + nt * 8 + (lane & 3) * 2;
            float* a = acc[mt][nt];
            if (!tstore) {
                if (n0 < N) {
                    float bs = bias1[n0] + (bias2 ? bias2[n0] : 0.0f);
                    C[(size_t)m0 * N + n0]       = a[0] + bs;
                    C[(size_t)(m0 + 8) * N + n0] = a[2] + bs;
                }
                if (n0 + 1 < N) {
                    float bs = bias1[n0 + 1] + (bias2 ? bias2[n0 + 1] : 0.0f);
                    C[(size_t)m0 * N + n0 + 1]       = a[1] + bs;
                    C[(size_t)(m0 + 8) * N + n0 + 1] = a[3] + bs;
                }
            } else {
                // transposed store: C[(t*N + n)*64 + b], m = b*512 + t; N mult of 128
                float bs0 = bias1[n0] + bias2[n0];
                float bs1 = bias1[n0 + 1] + bias2[n0 + 1];
                size_t o0 = ((size_t)(m0 & 511) * N + n0) * 64 + (m0 >> 9);
                int m8 = m0 + 8;
                size_t o8 = ((size_t)(m8 & 511) * N + n0) * 64 + (m8 >> 9);
                C[o0]      = a[0] + bs0;
                C[o0 + 64] = a[1] + bs1;
                C[o8]      = a[2] + bs0;
                C[o8 + 64] = a[3] + bs1;
            }
        }
    }
}

// ---------------- persistent tensor-core LSTM recurrence ----------------
#define LA_HI   0
#define LA_LO   50176           // 64 rows * 784B pitch
#define LW_HI   100352
#define LW_LO   119168          // 24 rows * 784B
#define LGATES  137984          // 64 * 26 floats
#define LCS     144640          // 384 floats
#define LHSTH   146176          // 384 bf16 (h-hi stage)
#define LHSTL   146944          // 384 bf16 (h-lo stage)
#define LSMEM   147712
#define PITCH   784

__global__ void __launch_bounds__(RTH, 1)
lstm_kernel(const float* __restrict__ Whh_f, const float* __restrict__ Whh_b)
{
    extern __shared__ char smem[];
    uint32_t sb = smem_u32(smem);
    float* gates_s = (float*)(smem + LGATES);
    float* c_s     = (float*)(smem + LCS);

    int cta = blockIdx.x;
    int dir = (cta >= NCD) ? 1 : 0;
    int ci  = cta - dir * NCD;
    const float* Whh = dir ? Whh_b : Whh_f;
    const float* xp  = dir ? g_xptb : g_xptf;
    int n0  = ci * CH;
    int tid = threadIdx.x;
    int lane = tid & 31, wid = tid >> 5;
    int mt = wid & 3;          // m-tile (16 b rows)
    int nt = wid >> 2;         // n-tile (8 gate rows)

    // ---- load + split Whh slice into SMEM (once) ----
    for (int idx = tid; idx < RR * HH; idx += RTH) {
        int r = idx / HH, k = idx - r * HH;
        int gi = r / CH, j = r - gi * CH;
        float v = Whh[(size_t)(gi * HH + n0 + j) * HH + k];
        __nv_bfloat16 h = __float2bfloat16(v);
        *(__nv_bfloat16*)(smem + LW_HI + r * PITCH + k * 2) = h;
        *(__nv_bfloat16*)(smem + LW_LO + r * PITCH + k * 2) =
            __float2bfloat16(v - __bfloat162float(h));
    }
    for (int idx = tid; idx < CH * BB; idx += RTH) c_s[idx] = 0.0f;
    __syncthreads();

    int cj = tid >> 6;         // 0..5
    int cb = tid & 63;

    int la  = lane & 15, lc4 = lane >> 4;
    uint32_t aAddrBase = sb + LA_HI + (mt * 16 + la) * PITCH + lc4 * 16;
    uint32_t bAddrBase = sb + LW_HI + ((lane >= 16) ? (LW_LO - LW_HI) : 0u)
                       + (nt * 8 + (lane & 7)) * PITCH + ((lane >> 3) & 1) * 16;

    // initial xp prefetch (transposed layout: [t][feat][b], lanes contiguous)
    float xg[4];
    {
        int t0 = dir ? (SS - 1) : 0;
        const float* xr = xp + ((size_t)t0 * FOURH + n0 + cj) * 64 + cb;
#pragma unroll
        for (int gi = 0; gi < 4; ++gi) xg[gi] = __ldg(xr + (size_t)gi * HH * 64);
    }

    for (int s = 0; s < SS; ++s) {
        int t = dir ? (SS - 1 - s) : s;
        int p = s & 1;
        int np = (s + 1) & 1;

        const char* srcH = (const char*)&g_hbhi[dir][p][0];
        const char* srcL = (const char*)&g_hblo[dir][p][0];
#pragma unroll
        for (int q = 0; q < 4; ++q) {
#pragma unroll
            for (int i = 0; i < 2; ++i) {
                int e = i * RTH + tid;            // 0..767
                int row = e / 12, cc = e - row * 12;
                uint32_t so = row * 768 + q * 192 + cc * 16;
                uint32_t doff = row * PITCH + q * 192 + cc * 16;
                cp16(sb + LA_HI + doff, srcH + so, true);
                cp16(sb + LA_LO + doff, srcL + so, true);
            }
            CP_COMMIT();
        }

        float acc[4] = {0.f, 0.f, 0.f, 0.f};
#pragma unroll
        for (int q = 0; q < 4; ++q) {
            if      (q == 0) CP_WAIT(3);
            else if (q == 1) CP_WAIT(2);
            else if (q == 2) CP_WAIT(1);
            else             CP_WAIT(0);
            __syncthreads();
#pragma unroll
            for (int kk = 0; kk < 6; ++kk) {
                int k16 = q * 6 + kk;
                uint32_t ka = aAddrBase + k16 * 32;
                uint32_t kb = bAddrBase + k16 * 32;
                uint32_t ah[4], al[4], bb[4];
                LDM4(ah, ka);
                LDM4(al, ka + (LA_LO - LA_HI));
                LDM4(bb, kb);                      // bb = {bh0, bh1, bl0, bl1}
                MMA(acc, ah, bb[0], bb[1]);
                MMA(acc, ah, bb[2], bb[3]);
                MMA(acc, al, bb[0], bb[1]);
            }
        }

        {
            int brow = mt * 16 + (lane >> 2);
            int rcol = nt * 8 + (lane & 3) * 2;
            *(float2*)&gates_s[brow * 26 + rcol]       = make_float2(acc[0], acc[1]);
            *(float2*)&gates_s[(brow + 8) * 26 + rcol] = make_float2(acc[2], acc[3]);
        }
        __syncthreads();

        // ---- cell update (1 cell per thread) ----
        {
            float ig = gates_s[cb * 26 + 0 * CH + cj] + xg[0];
            float fg = gates_s[cb * 26 + 1 * CH + cj] + xg[1];
            float gg = gates_s[cb * 26 + 2 * CH + cj] + xg[2];
            float og = gates_s[cb * 26 + 3 * CH + cj] + xg[3];
            float c  = c_s[tid];
            c = sigf(fg) * c + sigf(ig) * tanhfast(gg);
            float h = sigf(og) * tanhfast(c);
            c_s[tid] = c;
            __nv_bfloat16 hh = __float2bfloat16(h);
            __nv_bfloat16 hl = __float2bfloat16(h - __bfloat162float(hh));
            // stage h in SMEM for coalesced cooperative write
            ((__nv_bfloat16*)(smem + LHSTH))[cb * CH + cj] = hh;
            ((__nv_bfloat16*)(smem + LHSTL))[cb * CH + cj] = hl;
            // f1 transposed store: [t][feat][b] — lanes contiguous (64B/warp)
            size_t fo = ((size_t)t * K2H + dir * HH + n0 + cj) * 64 + cb;
            g_f1thi[fo] = hh;
            g_f1tlo[fo] = hl;
        }

        // ---- prefetch xp for next step ----
        if (s + 1 < SS) {
            int t1 = dir ? (SS - 2 - s) : (s + 1);
            const float* xr = xp + ((size_t)t1 * FOURH + n0 + cj) * 64 + cb;
#pragma unroll
            for (int gi = 0; gi < 4; ++gi) xg[gi] = __ldg(xr + (size_t)gi * HH * 64);
        }

        __syncthreads();   // h stage visible

        // ---- cooperative h write: 12B contiguous run per (comp, b) ----
        if (tid < 128) {
            int b = tid & 63;
            int comp = tid >> 6;
            const uint32_t* s3 = (const uint32_t*)(smem + (comp ? LHSTL : LHSTH) + b * 12);
            __nv_bfloat16* gdst = (comp ? &g_hblo[dir][np][0] : &g_hbhi[dir][np][0])
                                  + b * HH + n0;
            uint32_t w0 = s3[0], w1 = s3[1], w2 = s3[2];
            ((uint32_t*)gdst)[0] = w0;
            ((uint32_t*)gdst)[1] = w1;
            ((uint32_t*)gdst)[2] = w2;
        }

        __threadfence();
        __syncthreads();
        if (wid == 0) {
            if (lane == 0) atomicAdd(&g_bar[dir][s][ci & 7], 1u);
            unsigned done;
            do {
                unsigned v = 0;
                if (lane < 8)
                    asm volatile("ld.global.cg.u32 %0, [%1];"
                                 : "=r"(v) : "l"(&g_bar[dir][s][lane]));
                v += __shfl_xor_sync(0xffffffffu, v, 1);
                v += __shfl_xor_sync(0xffffffffu, v, 2);
                v += __shfl_xor_sync(0xffffffffu, v, 4);
                done = __shfl_sync(0xffffffffu, v, 0);
            } while (done < (unsigned)NCD);
        }
        __syncthreads();
    }
}

// ---------------- f1t [t][feat][b] -> f1 [b][t][feat] transpose ----------------
// Matrix R x 64 (R = SS*K2H) -> 64 x R, 64x64 bf16 tiles.
__global__ void tr_kernel()
{
    __shared__ unsigned short tile2[64][66];   // [b][i-within-tile]
    const int R = SS * K2H;                    // 393216
    const __nv_bfloat16* src = blockIdx.z ? g_f1tlo : g_f1thi;
    __nv_bfloat16*       dst = blockIdx.z ? g_f1lo  : g_f1hi;
    int i0 = blockIdx.x * 64;
    int tid = threadIdx.x;

#pragma unroll
    for (int ph = 0; ph < 8; ++ph) {
        int idx = ph * 256 + tid;
        int r  = idx >> 5;          // i-row within tile (0..63)
        int cl = idx & 31;          // u32 chunk (2 bf16) in b-dim
        uint32_t w = *(const uint32_t*)(src + (size_t)(i0 + r) * 64 + cl * 2);
        tile2[cl * 2 + 0][r] = (unsigned short)(w & 0xffffu);
        tile2[cl * 2 + 1][r] = (unsigned short)(w >> 16);
    }
    __syncthreads();

#pragma unroll
    for (int ph = 0; ph < 8; ++ph) {
        int idx = ph * 256 + tid;
        int b  = idx >> 5;          // output row (0..63)
        int cl = idx & 31;          // u32 chunk in i-dim
        uint32_t w = *(const uint32_t*)&tile2[b][cl * 2];
        *(uint32_t*)(dst + (size_t)b * R + i0 + cl * 2) = w;
    }
}

// ---------------- launcher ----------------
extern "C" void kernel_launch(void* const* d_in, const int* in_sizes, int n_in,
                              void* d_out, int out_size)
{
    const float* f0     = (const float*)d_in[0];
    const int*   counts = (const int*)  d_in[1];
    const float* Wih_f  = (const float*)d_in[2];
    const float* Whh_f  = (const float*)d_in[3];
    const float* bih_f  = (const float*)d_in[4];
    const float* bhh_f  = (const float*)d_in[5];
    const float* Wih_b  = (const float*)d_in[6];
    const float* Whh_b  = (const float*)d_in[7];
    const float* bih_b  = (const float*)d_in[8];
    const float* bhh_b  = (const float*)d_in[9];
    const float* Wlin   = (const float*)d_in[10];
    const float* blin   = (const float*)d_in[11];
    float* out = (float*)d_out;

    void* p;
    cudaGetSymbolAddress(&p, g_xhi);     __nv_bfloat16* xhi = (__nv_bfloat16*)p;
    cudaGetSymbolAddress(&p, g_xlo);     __nv_bfloat16* xlo = (__nv_bfloat16*)p;
    cudaGetSymbolAddress(&p, g_xptf);    float* gxptf = (float*)p;
    cudaGetSymbolAddress(&p, g_xptb);    float* gxptb = (float*)p;
    cudaGetSymbolAddress(&p, g_f1hi);    __nv_bfloat16* f1hi = (__nv_bfloat16*)p;
    cudaGetSymbolAddress(&p, g_f1lo);    __nv_bfloat16* f1lo = (__nv_bfloat16*)p;
    cudaGetSymbolAddress(&p, g_wihf_hi); __nv_bfloat16* wfh = (__nv_bfloat16*)p;
    cudaGetSymbolAddress(&p, g_wihf_lo); __nv_bfloat16* wfl = (__nv_bfloat16*)p;
    cudaGetSymbolAddress(&p, g_wihb_hi); __nv_bfloat16* wbh = (__nv_bfloat16*)p;
    cudaGetSymbolAddress(&p, g_wihb_lo); __nv_bfloat16* wbl = (__nv_bfloat16*)p;
    cudaGetSymbolAddress(&p, g_wlin_hi); __nv_bfloat16* wlh = (__nv_bfloat16*)p;
    cudaGetSymbolAddress(&p, g_wlin_lo); __nv_bfloat16* wll = (__nv_bfloat16*)p;

    cudaFuncSetAttribute(lstm_kernel, cudaFuncAttributeMaxDynamicSharedMemorySize, LSMEM);
    cudaFuncSetAttribute(gemm3_kernel, cudaFuncAttributeMaxDynamicSharedMemorySize, 2 * STGB);

    int nw = FOURH * DD;
    int nl = CC * K2H;
    int ncvt = 2 * nw + nl;
    initcvt_kernel<<<(ncvt + 255) / 256, 256>>>(Wih_f, wfh, wfl, nw,
                                                Wih_b, wbh, wbl, nw,
                                                Wlin,  wlh, wll, nl);
    pool_kernel<<<BB, 256>>>(f0, counts, xhi, xlo);

    dim3 gproj(FOURH / 128, MM / 128);   // 12 x 256
    gemm3_kernel<<<gproj, 256, 2 * STGB>>>(xhi, xlo, wfh, wfl, bih_f, bhh_f,
                                           gxptf, FOURH, DD, 1);
    gemm3_kernel<<<gproj, 256, 2 * STGB>>>(xhi, xlo, wbh, wbl, bih_b, bhh_b,
                                           gxptb, FOURH, DD, 1);

    lstm_kernel<<<2 * NCD, RTH, LSMEM>>>(Whh_f, Whh_b);

    dim3 gtr(SS * K2H / 64, 1, 2);       // 6144 x 1 x 2
    tr_kernel<<<gtr, 256>>>();

    dim3 gout((CC + 127) / 128, MM / 128);  // 4 x 256
    gemm3_kernel<<<gout, 256, 2 * STGB>>>(f1hi, f1lo, wlh, wll, blin, nullptr,
                                          out, CC, K2H, 0);
}

// round 13
// speedup vs baseline: 1.7595x; 1.1723x over previous
#include <cuda_runtime.h>
#include <cuda_bf16.h>
#include <math.h>
#include <stdint.h>

// Problem dims
#define BB   64
#define SS   512
#define DD   768
#define WW   256
#define HH   384
#define FOURH 1536
#define CC   425
#define K2H  768
#define MM   (BB*SS)      // 32768 rows

// Recurrence config
#define NCD   64          // CTAs per direction (128 total)
#define CH    6           // h-indices per CTA (64*6 = 384)
#define RR    24          // gate rows per CTA (4 gates * CH)
#define RTH   384         // 12 warps: 4 m-tiles x 3 n-tiles

// -------- scratch (device globals; no allocation allowed) --------
__device__ __nv_bfloat16 g_xhi[MM * DD];
__device__ __nv_bfloat16 g_xlo[MM * DD];
__device__ float g_xptf[MM * FOURH];              // proj fwd, layout [t][feat][b]
__device__ float g_xptb[MM * FOURH];              // proj bwd, layout [t][feat][b]
__device__ __nv_bfloat16 g_f1thi[MM * K2H];       // [t][feat][b]
__device__ __nv_bfloat16 g_f1tlo[MM * K2H];
__device__ __nv_bfloat16 g_f1hi[MM * K2H];        // [b][t][feat] (post-transpose)
__device__ __nv_bfloat16 g_f1lo[MM * K2H];
__device__ __nv_bfloat16 g_hbhi[2][2][BB * HH];   // [dir][parity][b*384+k]
__device__ __nv_bfloat16 g_hblo[2][2][BB * HH];
__device__ unsigned g_bar[2][SS][8];              // split barrier counters
__device__ __nv_bfloat16 g_wihf_hi[FOURH * DD], g_wihf_lo[FOURH * DD];
__device__ __nv_bfloat16 g_wihb_hi[FOURH * DD], g_wihb_lo[FOURH * DD];
__device__ __nv_bfloat16 g_wlin_hi[CC * K2H],  g_wlin_lo[CC * K2H];

// ---------------- small helpers ----------------
__device__ __forceinline__ uint32_t smem_u32(const void* p) {
    uint32_t a;
    asm("{ .reg .u64 t; cvta.to.shared.u64 t, %1; cvt.u32.u64 %0, t; }"
        : "=r"(a) : "l"(p));
    return a;
}
__device__ __forceinline__ void cp16(uint32_t d, const void* s, bool v) {
    int sz = v ? 16 : 0;
    asm volatile("cp.async.cg.shared.global [%0], [%1], 16, %2;\n"
                 :: "r"(d), "l"(s), "r"(sz));
}
#define CP_COMMIT() asm volatile("cp.async.commit_group;\n")
#define CP_WAIT(n)  asm volatile("cp.async.wait_group %0;\n" :: "n"(n))

#define LDM4(r, addr) \
    asm volatile("ldmatrix.sync.aligned.m8n8.x4.shared.b16 {%0,%1,%2,%3}, [%4];" \
        : "=r"((r)[0]), "=r"((r)[1]), "=r"((r)[2]), "=r"((r)[3]) : "r"(addr))

#define MMA(d, a, b0, b1) \
    asm volatile("mma.sync.aligned.m16n8k16.row.col.f32.bf16.bf16.f32 " \
        "{%0,%1,%2,%3},{%4,%5,%6,%7},{%8,%9},{%0,%1,%2,%3};" \
        : "+f"((d)[0]), "+f"((d)[1]), "+f"((d)[2]), "+f"((d)[3]) \
        : "r"((a)[0]), "r"((a)[1]), "r"((a)[2]), "r"((a)[3]), "r"(b0), "r"(b1))

// fast activations (clamped; rel err ~1e-6)
__device__ __forceinline__ float sigf(float x) {
    x = fminf(fmaxf(x, -30.0f), 30.0f);
    return __fdividef(1.0f, 1.0f + __expf(-x));
}
__device__ __forceinline__ float tanhfast(float x) {
    x = fminf(fmaxf(x, -15.0f), 15.0f);
    float e = __expf(2.0f * x);
    return __fdividef(e - 1.0f, e + 1.0f);
}

// ---------------- fused init (h state, barriers) + weight hi/lo split ------
__global__ void initcvt_kernel(const float* __restrict__ in0, __nv_bfloat16* __restrict__ hi0,
                               __nv_bfloat16* __restrict__ lo0, int n0,
                               const float* __restrict__ in1, __nv_bfloat16* __restrict__ hi1,
                               __nv_bfloat16* __restrict__ lo1, int n1,
                               const float* __restrict__ in2, __nv_bfloat16* __restrict__ hi2,
                               __nv_bfloat16* __restrict__ lo2, int n2)
{
    int gid = blockIdx.x * blockDim.x + threadIdx.x;

    if (gid < 2 * BB * HH) {
        g_hbhi[gid / (BB * HH)][0][gid % (BB * HH)] = __float2bfloat16(0.0f);
        g_hblo[gid / (BB * HH)][0][gid % (BB * HH)] = __float2bfloat16(0.0f);
    }
    if (gid < 2 * SS * 8) (&g_bar[0][0][0])[gid] = 0u;

    int i = gid;
    const float* in; __nv_bfloat16 *hi, *lo;
    if (i < n0)                { in = in0; hi = hi0; lo = lo0; }
    else if (i < n0 + n1)      { i -= n0; in = in1; hi = hi1; lo = lo1; }
    else if (i < n0 + n1 + n2) { i -= n0 + n1; in = in2; hi = hi2; lo = lo2; }
    else return;
    float v = in[i];
    __nv_bfloat16 h = __float2bfloat16(v);
    hi[i] = h;
    lo[i] = __float2bfloat16(v - __bfloat162float(h));
}

// ---------------- segment mean pool (writes split bf16) ----------------
__global__ void pool_kernel(const float* __restrict__ f0,
                            const int*   __restrict__ counts,
                            __nv_bfloat16* __restrict__ xhi,
                            __nv_bfloat16* __restrict__ xlo)
{
    __shared__ int s_start[WW];
    __shared__ int s_cnt[WW];
    int b = blockIdx.x;
    int tid = threadIdx.x;
    if (tid == 0) {
        int run = 0;
        for (int j = 0; j < WW; ++j) {
            int c = counts[b * WW + j];
            s_start[j] = run; s_cnt[j] = c; run += c;
        }
    }
    __syncthreads();
    const float* fb = f0 + (size_t)b * SS * DD;
    __nv_bfloat16* xh = xhi + (size_t)b * SS * DD;
    __nv_bfloat16* xl = xlo + (size_t)b * SS * DD;
    for (int idx = tid; idx < WW * DD; idx += blockDim.x) {
        int j = idx / DD, d = idx - j * DD;
        int st = s_start[j], c = s_cnt[j];
        float v = 0.0f;
        for (int p = 0; p < c; ++p) v += fb[(size_t)(st + p) * DD + d];
        v /= (float)c;
        __nv_bfloat16 h = __float2bfloat16(v);
        xh[idx] = h;
        xl[idx] = __float2bfloat16(v - __bfloat162float(h));
    }
    for (int idx = tid; idx < (SS - WW) * DD; idx += blockDim.x) {
        float v = fb[WW * DD + idx];
        __nv_bfloat16 h = __float2bfloat16(v);
        xh[WW * DD + idx] = h;
        xl[WW * DD + idx] = __float2bfloat16(v - __bfloat162float(h));
    }
}

// ---------------- split-bf16 tensor-core GEMM (mma.sync) ----------------
// C = (Ahi+Alo)*(Bhi+Blo)^T + bias1 + bias2 ; 3 terms, fp32 accumulate.
// 128x128 tile, BK=32, 256 threads, 64x32 warp tiles.
// tstore=0: C[m][n] row-major, tile = 128 consecutive m.
// tstore=1: C[(t*N+n)*64 + b] with m = b*512 + t; a tile covers 64 b x 2 t
//           (row-gathered A) so warp stores hit full 32B sectors.
#define ARRB  (128 * 80)
#define STGB  (4 * ARRB)

__global__ void __launch_bounds__(256, 1)
gemm3_kernel(const __nv_bfloat16* __restrict__ Ahi, const __nv_bfloat16* __restrict__ Alo,
             const __nv_bfloat16* __restrict__ Bhi, const __nv_bfloat16* __restrict__ Blo,
             const float* __restrict__ bias1, const float* __restrict__ bias2,
             float* __restrict__ C, int N, int K, int tstore)
{
    extern __shared__ char smem[];
    uint32_t sb = smem_u32(smem);
    int tid = threadIdx.x, lane = tid & 31, wid = tid >> 5;
    int wm = wid >> 2, wn = wid & 3;
    int bm = blockIdx.y, bn = blockIdx.x;

    int lr = tid >> 1;
    int lc = (tid & 1) * 2;
    // A row gather: tstore tiles cover 64 b-values x 2 t-values
    int arow = tstore ? ((lr & 63) * SS + bm * 2 + (lr >> 6))
                      : (bm * 128 + lr);
    int brow = bn * 128 + lr;
    bool bv  = brow < N;
    const __nv_bfloat16* pAh = Ahi + (size_t)arow * K;
    const __nv_bfloat16* pAl = Alo + (size_t)arow * K;
    const __nv_bfloat16* pBh = Bhi + (size_t)(bv ? brow : 0) * K;
    const __nv_bfloat16* pBl = Blo + (size_t)(bv ? brow : 0) * K;
    uint32_t sd = sb + lr * 80 + lc * 16;

    float acc[4][4][4];
#pragma unroll
    for (int a = 0; a < 4; ++a)
#pragma unroll
        for (int b = 0; b < 4; ++b)
#pragma unroll
            for (int c = 0; c < 4; ++c) acc[a][b][c] = 0.0f;

    int KT = K >> 5;

    {
        uint32_t d = sd;
#pragma unroll
        for (int cc = 0; cc < 2; ++cc) {
            cp16(d + cc * 16 + 0 * ARRB, pAh + (lc + cc) * 8, true);
            cp16(d + cc * 16 + 1 * ARRB, pAl + (lc + cc) * 8, true);
            cp16(d + cc * 16 + 2 * ARRB, pBh + (lc + cc) * 8, bv);
            cp16(d + cc * 16 + 3 * ARRB, pBl + (lc + cc) * 8, bv);
        }
        CP_COMMIT();
    }

    int la  = lane & 15, lc4 = lane >> 4;
    int lb  = (lane & 7) + ((lane & 16) >> 1);
    int lbc = (lane >> 3) & 1;

    for (int i = 0; i < KT; ++i) {
        CP_WAIT(0);
        __syncthreads();
        if (i + 1 < KT) {
            int ko = (i + 1) << 5;
            uint32_t d = sd + ((i + 1) & 1) * STGB;
#pragma unroll
            for (int cc = 0; cc < 2; ++cc) {
                cp16(d + cc * 16 + 0 * ARRB, pAh + ko + (lc + cc) * 8, true);
                cp16(d + cc * 16 + 1 * ARRB, pAl + ko + (lc + cc) * 8, true);
                cp16(d + cc * 16 + 2 * ARRB, pBh + ko + (lc + cc) * 8, bv);
                cp16(d + cc * 16 + 3 * ARRB, pBl + ko + (lc + cc) * 8, bv);
            }
            CP_COMMIT();
        }
        uint32_t st = sb + (i & 1) * STGB;
#pragma unroll
        for (int kh = 0; kh < 2; ++kh) {
            uint32_t aaddr = st + (wm * 64 + la) * 80 + (kh * 2 + lc4) * 16;
            uint32_t ah[4][4], al[4][4];
#pragma unroll
            for (int mt = 0; mt < 4; ++mt) {
                LDM4(ah[mt], aaddr + mt * 1280);
                LDM4(al[mt], aaddr + mt * 1280 + ARRB);
            }
            uint32_t bbase = st + 2 * ARRB + (wn * 32 + lb) * 80 + (kh * 2 + lbc) * 16;
            uint32_t bh[2][4], bl[2][4];
#pragma unroll
            for (int ntp = 0; ntp < 2; ++ntp) {
                LDM4(bh[ntp], bbase + ntp * 1280);
                LDM4(bl[ntp], bbase + ntp * 1280 + ARRB);
            }
#pragma unroll
            for (int mt = 0; mt < 4; ++mt)
#pragma unroll
                for (int ntp = 0; ntp < 2; ++ntp) {
                    MMA(acc[mt][2 * ntp + 0], ah[mt], bh[ntp][0], bh[ntp][1]);
                    MMA(acc[mt][2 * ntp + 1], ah[mt], bh[ntp][2], bh[ntp][3]);
                }
#pragma unroll
            for (int mt = 0; mt < 4; ++mt)
#pragma unroll
                for (int ntp = 0; ntp < 2; ++ntp) {
                    MMA(acc[mt][2 * ntp + 0], ah[mt], bl[ntp][0], bl[ntp][1]);
                    MMA(acc[mt][2 * ntp + 1], ah[mt], bl[ntp][2], bl[ntp][3]);
                }
#pragma unroll
            for (int mt = 0; mt < 4; ++mt)
#pragma unroll
                for (int ntp = 0; ntp < 2; ++ntp) {
                    MMA(acc[mt][2 * ntp + 0], al[mt], bh[ntp][0], bh[ntp][1]);
                    MMA(acc[mt][2 * ntp + 1], al[mt], bh[ntp][2], bh[ntp][3]);
                }
        }
        __syncthreads();
    }

    // epilogue
#pragma unroll
    for (int mt = 0; mt < 4; ++mt) {
        int r0_ = wm * 64 + mt * 16 + (lane >> 2);      // tile row 0..127
#pragma unroll
        for (int nt = 0; nt < 4; ++nt) {
            int n0 = bn * 128 + wn * 32 + nt * 8 + (lane & 3) * 2;
            float* a = acc[mt][nt];
            if (!tstore) {
                int m0 = bm * 128 + r0_;
                if (n0 < N) {
                    float bs = bias1[n0] + (bias2 ? bias2[n0] : 0.0f);
                    C[(size_t)m0 * N + n0]       = a[0] + bs;
                    C[(size_t)(m0 + 8) * N + n0] = a[2] + bs;
                }
                if (n0 + 1 < N) {
                    float bs = bias1[n0 + 1] + (bias2 ? bias2[n0 + 1] : 0.0f);
                    C[(size_t)m0 * N + n0 + 1]       = a[1] + bs;
                    C[(size_t)(m0 + 8) * N + n0 + 1] = a[3] + bs;
                }
            } else {
                // tile row r -> b = r&63, t = bm*2 + (r>>6). r and r+8 share t.
                int b_ = r0_ & 63;
                int t_ = bm * 2 + (r0_ >> 6);
                float bs0 = bias1[n0] + bias2[n0];
                float bs1 = bias1[n0 + 1] + bias2[n0 + 1];
                size_t o0 = ((size_t)t_ * N + n0) * 64 + b_;
                C[o0]          = a[0] + bs0;   // lanes: 8 consecutive b per sector
                C[o0 + 64]     = a[1] + bs1;
                C[o0 + 8]      = a[2] + bs0;
                C[o0 + 64 + 8] = a[3] + bs1;
            }
        }
    }
}

// ---------------- persistent tensor-core LSTM recurrence ----------------
#define LA_HI   0
#define LA_LO   50176           // 64 rows * 784B pitch
#define LW_HI   100352
#define LW_LO   119168          // 24 rows * 784B
#define LGATES  137984          // 64 * 26 floats
#define LCS     144640          // 384 floats
#define LHSTH   146176          // 384 bf16 (h-hi stage)
#define LHSTL   146944          // 384 bf16 (h-lo stage)
#define LSMEM   147712
#define PITCH   784

__global__ void __launch_bounds__(RTH, 1)
lstm_kernel(const float* __restrict__ Whh_f, const float* __restrict__ Whh_b)
{
    extern __shared__ char smem[];
    uint32_t sb = smem_u32(smem);
    float* gates_s = (float*)(smem + LGATES);
    float* c_s     = (float*)(smem + LCS);

    int cta = blockIdx.x;
    int dir = (cta >= NCD) ? 1 : 0;
    int ci  = cta - dir * NCD;
    const float* Whh = dir ? Whh_b : Whh_f;
    const float* xp  = dir ? g_xptb : g_xptf;
    int n0  = ci * CH;
    int tid = threadIdx.x;
    int lane = tid & 31, wid = tid >> 5;
    int mt = wid & 3;          // m-tile (16 b rows)
    int nt = wid >> 2;         // n-tile (8 gate rows)

    // ---- load + split Whh slice into SMEM (once) ----
    for (int idx = tid; idx < RR * HH; idx += RTH) {
        int r = idx / HH, k = idx - r * HH;
        int gi = r / CH, j = r - gi * CH;
        float v = Whh[(size_t)(gi * HH + n0 + j) * HH + k];
        __nv_bfloat16 h = __float2bfloat16(v);
        *(__nv_bfloat16*)(smem + LW_HI + r * PITCH + k * 2) = h;
        *(__nv_bfloat16*)(smem + LW_LO + r * PITCH + k * 2) =
            __float2bfloat16(v - __bfloat162float(h));
    }
    for (int idx = tid; idx < CH * BB; idx += RTH) c_s[idx] = 0.0f;
    __syncthreads();

    int cj = tid >> 6;         // 0..5
    int cb = tid & 63;

    int la  = lane & 15, lc4 = lane >> 4;
    uint32_t aAddrBase = sb + LA_HI + (mt * 16 + la) * PITCH + lc4 * 16;
    uint32_t bAddrBase = sb + LW_HI + ((lane >= 16) ? (LW_LO - LW_HI) : 0u)
                       + (nt * 8 + (lane & 7)) * PITCH + ((lane >> 3) & 1) * 16;

    // initial xp prefetch (transposed layout: [t][feat][b], lanes contiguous)
    float xg[4];
    {
        int t0 = dir ? (SS - 1) : 0;
        const float* xr = xp + ((size_t)t0 * FOURH + n0 + cj) * 64 + cb;
#pragma unroll
        for (int gi = 0; gi < 4; ++gi) xg[gi] = __ldg(xr + (size_t)gi * HH * 64);
    }

    for (int s = 0; s < SS; ++s) {
        int t = dir ? (SS - 1 - s) : s;
        int p = s & 1;
        int np = (s + 1) & 1;

        const char* srcH = (const char*)&g_hbhi[dir][p][0];
        const char* srcL = (const char*)&g_hblo[dir][p][0];
#pragma unroll
        for (int q = 0; q < 4; ++q) {
#pragma unroll
            for (int i = 0; i < 2; ++i) {
                int e = i * RTH + tid;            // 0..767
                int row = e / 12, cc = e - row * 12;
                uint32_t so = row * 768 + q * 192 + cc * 16;
                uint32_t doff = row * PITCH + q * 192 + cc * 16;
                cp16(sb + LA_HI + doff, srcH + so, true);
                cp16(sb + LA_LO + doff, srcL + so, true);
            }
            CP_COMMIT();
        }

        float acc[4] = {0.f, 0.f, 0.f, 0.f};
#pragma unroll
        for (int q = 0; q < 4; ++q) {
            if      (q == 0) CP_WAIT(3);
            else if (q == 1) CP_WAIT(2);
            else if (q == 2) CP_WAIT(1);
            else             CP_WAIT(0);
            __syncthreads();
#pragma unroll
            for (int kk = 0; kk < 6; ++kk) {
                int k16 = q * 6 + kk;
                uint32_t ka = aAddrBase + k16 * 32;
                uint32_t kb = bAddrBase + k16 * 32;
                uint32_t ah[4], al[4], bb[4];
                LDM4(ah, ka);
                LDM4(al, ka + (LA_LO - LA_HI));
                LDM4(bb, kb);                      // bb = {bh0, bh1, bl0, bl1}
                MMA(acc, ah, bb[0], bb[1]);
                MMA(acc, ah, bb[2], bb[3]);
                MMA(acc, al, bb[0], bb[1]);
            }
        }

        {
            int brow = mt * 16 + (lane >> 2);
            int rcol = nt * 8 + (lane & 3) * 2;
            *(float2*)&gates_s[brow * 26 + rcol]       = make_float2(acc[0], acc[1]);
            *(float2*)&gates_s[(brow + 8) * 26 + rcol] = make_float2(acc[2], acc[3]);
        }
        __syncthreads();

        // ---- cell update (1 cell per thread) ----
        {
            float ig = gates_s[cb * 26 + 0 * CH + cj] + xg[0];
            float fg = gates_s[cb * 26 + 1 * CH + cj] + xg[1];
            float gg = gates_s[cb * 26 + 2 * CH + cj] + xg[2];
            float og = gates_s[cb * 26 + 3 * CH + cj] + xg[3];
            float c  = c_s[tid];
            c = sigf(fg) * c + sigf(ig) * tanhfast(gg);
            float h = sigf(og) * tanhfast(c);
            c_s[tid] = c;
            __nv_bfloat16 hh = __float2bfloat16(h);
            __nv_bfloat16 hl = __float2bfloat16(h - __bfloat162float(hh));
            // stage h in SMEM for coalesced cooperative write
            ((__nv_bfloat16*)(smem + LHSTH))[cb * CH + cj] = hh;
            ((__nv_bfloat16*)(smem + LHSTL))[cb * CH + cj] = hl;
            // f1 transposed store: [t][feat][b] — lanes contiguous (64B/warp)
            size_t fo = ((size_t)t * K2H + dir * HH + n0 + cj) * 64 + cb;
            g_f1thi[fo] = hh;
            g_f1tlo[fo] = hl;
        }

        // ---- prefetch xp for next step ----
        if (s + 1 < SS) {
            int t1 = dir ? (SS - 2 - s) : (s + 1);
            const float* xr = xp + ((size_t)t1 * FOURH + n0 + cj) * 64 + cb;
#pragma unroll
            for (int gi = 0; gi < 4; ++gi) xg[gi] = __ldg(xr + (size_t)gi * HH * 64);
        }

        __syncthreads();   // h stage visible

        // ---- cooperative h write: 12B contiguous run per (comp, b) ----
        if (tid < 128) {
            int b = tid & 63;
            int comp = tid >> 6;
            const uint32_t* s3 = (const uint32_t*)(smem + (comp ? LHSTL : LHSTH) + b * 12);
            __nv_bfloat16* gdst = (comp ? &g_hblo[dir][np][0] : &g_hbhi[dir][np][0])
                                  + b * HH + n0;
            uint32_t w0 = s3[0], w1 = s3[1], w2 = s3[2];
            ((uint32_t*)gdst)[0] = w0;
            ((uint32_t*)gdst)[1] = w1;
            ((uint32_t*)gdst)[2] = w2;
        }

        __threadfence();
        __syncthreads();
        if (wid == 0) {
            if (lane == 0) atomicAdd(&g_bar[dir][s][ci & 7], 1u);
            unsigned done;
            do {
                unsigned v = 0;
                if (lane < 8)
                    asm volatile("ld.global.cg.u32 %0, [%1];"
                                 : "=r"(v) : "l"(&g_bar[dir][s][lane]));
                v += __shfl_xor_sync(0xffffffffu, v, 1);
                v += __shfl_xor_sync(0xffffffffu, v, 2);
                v += __shfl_xor_sync(0xffffffffu, v, 4);
                done = __shfl_sync(0xffffffffu, v, 0);
            } while (done < (unsigned)NCD);
        }
        __syncthreads();
    }
}

// ---------------- f1t [t][feat][b] -> f1 [b][t][feat] transpose ----------------
// Matrix R x 64 (R = SS*K2H) -> 64 x R, 64x64 bf16 tiles.
__global__ void tr_kernel()
{
    __shared__ unsigned short tile2[64][66];   // [b][i-within-tile]
    const int R = SS * K2H;                    // 393216
    const __nv_bfloat16* src = blockIdx.z ? g_f1tlo : g_f1thi;
    __nv_bfloat16*       dst = blockIdx.z ? g_f1lo  : g_f1hi;
    int i0 = blockIdx.x * 64;
    int tid = threadIdx.x;

#pragma unroll
    for (int ph = 0; ph < 8; ++ph) {
        int idx = ph * 256 + tid;
        int r  = idx >> 5;          // i-row within tile (0..63)
        int cl = idx & 31;          // u32 chunk (2 bf16) in b-dim
        uint32_t w = *(const uint32_t*)(src + (size_t)(i0 + r) * 64 + cl * 2);
        tile2[cl * 2 + 0][r] = (unsigned short)(w & 0xffffu);
        tile2[cl * 2 + 1][r] = (unsigned short)(w >> 16);
    }
    __syncthreads();

#pragma unroll
    for (int ph = 0; ph < 8; ++ph) {
        int idx = ph * 256 + tid;
        int b  = idx >> 5;          // output row (0..63)
        int cl = idx & 31;          // u32 chunk in i-dim
        uint32_t w = *(const uint32_t*)&tile2[b][cl * 2];
        *(uint32_t*)(dst + (size_t)b * R + i0 + cl * 2) = w;
    }
}

// ---------------- launcher ----------------
extern "C" void kernel_launch(void* const* d_in, const int* in_sizes, int n_in,
                              void* d_out, int out_size)
{
    const float* f0     = (const float*)d_in[0];
    const int*   counts = (const int*)  d_in[1];
    const float* Wih_f  = (const float*)d_in[2];
    const float* Whh_f  = (const float*)d_in[3];
    const float* bih_f  = (const float*)d_in[4];
    const float* bhh_f  = (const float*)d_in[5];
    const float* Wih_b  = (const float*)d_in[6];
    const float* Whh_b  = (const float*)d_in[7];
    const float* bih_b  = (const float*)d_in[8];
    const float* bhh_b  = (const float*)d_in[9];
    const float* Wlin   = (const float*)d_in[10];
    const float* blin   = (const float*)d_in[11];
    float* out = (float*)d_out;

    void* p;
    cudaGetSymbolAddress(&p, g_xhi);     __nv_bfloat16* xhi = (__nv_bfloat16*)p;
    cudaGetSymbolAddress(&p, g_xlo);     __nv_bfloat16* xlo = (__nv_bfloat16*)p;
    cudaGetSymbolAddress(&p, g_xptf);    float* gxptf = (float*)p;
    cudaGetSymbolAddress(&p, g_xptb);    float* gxptb = (float*)p;
    cudaGetSymbolAddress(&p, g_f1hi);    __nv_bfloat16* f1hi = (__nv_bfloat16*)p;
    cudaGetSymbolAddress(&p, g_f1lo);    __nv_bfloat16* f1lo = (__nv_bfloat16*)p;
    cudaGetSymbolAddress(&p, g_wihf_hi); __nv_bfloat16* wfh = (__nv_bfloat16*)p;
    cudaGetSymbolAddress(&p, g_wihf_lo); __nv_bfloat16* wfl = (__nv_bfloat16*)p;
    cudaGetSymbolAddress(&p, g_wihb_hi); __nv_bfloat16* wbh = (__nv_bfloat16*)p;
    cudaGetSymbolAddress(&p, g_wihb_lo); __nv_bfloat16* wbl = (__nv_bfloat16*)p;
    cudaGetSymbolAddress(&p, g_wlin_hi); __nv_bfloat16* wlh = (__nv_bfloat16*)p;
    cudaGetSymbolAddress(&p, g_wlin_lo); __nv_bfloat16* wll = (__nv_bfloat16*)p;

    cudaFuncSetAttribute(lstm_kernel, cudaFuncAttributeMaxDynamicSharedMemorySize, LSMEM);
    cudaFuncSetAttribute(gemm3_kernel, cudaFuncAttributeMaxDynamicSharedMemorySize, 2 * STGB);

    int nw = FOURH * DD;
    int nl = CC * K2H;
    int ncvt = 2 * nw + nl;
    initcvt_kernel<<<(ncvt + 255) / 256, 256>>>(Wih_f, wfh, wfl, nw,
                                                Wih_b, wbh, wbl, nw,
                                                Wlin,  wlh, wll, nl);
    pool_kernel<<<BB, 256>>>(f0, counts, xhi, xlo);

    dim3 gproj(FOURH / 128, MM / 128);   // 12 x 256
    gemm3_kernel<<<gproj, 256, 2 * STGB>>>(xhi, xlo, wfh, wfl, bih_f, bhh_f,
                                           gxptf, FOURH, DD, 1);
    gemm3_kernel<<<gproj, 256, 2 * STGB>>>(xhi, xlo, wbh, wbl, bih_b, bhh_b,
                                           gxptb, FOURH, DD, 1);

    lstm_kernel<<<2 * NCD, RTH, LSMEM>>>(Whh_f, Whh_b);

    dim3 gtr(SS * K2H / 64, 1, 2);       // 6144 x 1 x 2
    tr_kernel<<<gtr, 256>>>();

    dim3 gout((CC + 127) / 128, MM / 128);  // 4 x 256
    gemm3_kernel<<<gout, 256, 2 * STGB>>>(f1hi, f1lo, wlh, wll, blin, nullptr,
                                          out, CC, K2H, 0);
}

// round 14
// speedup vs baseline: 1.7804x; 1.0119x over previous
#include <cuda_runtime.h>
#include <cuda_bf16.h>
#include <math.h>
#include <stdint.h>

// Problem dims
#define BB   64
#define SS   512
#define DD   768
#define WW   256
#define HH   384
#define FOURH 1536
#define CC   425
#define K2H  768
#define MM   (BB*SS)      // 32768 rows

// Recurrence config
#define NCD   64          // CTAs per direction (128 total)
#define CH    6           // h-indices per CTA (64*6 = 384)
#define RR    24          // gate rows per CTA (4 gates * CH)
#define RTH   384         // 12 warps: 4 m-tiles x 3 n-tiles

// -------- scratch (device globals; no allocation allowed) --------
__device__ __nv_bfloat16 g_xhi[MM * DD];
__device__ __nv_bfloat16 g_xlo[MM * DD];
__device__ float g_xptf[MM * FOURH];              // proj fwd, layout [t][feat][b]
__device__ float g_xptb[MM * FOURH];              // proj bwd, layout [t][feat][b]
__device__ __nv_bfloat16 g_f1thi[MM * K2H];       // [t][feat][b]
__device__ __nv_bfloat16 g_f1tlo[MM * K2H];
__device__ __nv_bfloat16 g_f1hi[MM * K2H];        // [b][t][feat] (post-transpose)
__device__ __nv_bfloat16 g_f1lo[MM * K2H];
__device__ __nv_bfloat16 g_hbhi[2][2][BB * HH];   // [dir][parity][b*384+k]
__device__ __nv_bfloat16 g_hblo[2][2][BB * HH];
__device__ unsigned g_bar[2][SS][4];              // per-step per-group counters
__device__ __nv_bfloat16 g_wihf_hi[FOURH * DD], g_wihf_lo[FOURH * DD];
__device__ __nv_bfloat16 g_wihb_hi[FOURH * DD], g_wihb_lo[FOURH * DD];
__device__ __nv_bfloat16 g_wlin_hi[CC * K2H],  g_wlin_lo[CC * K2H];

// ---------------- small helpers ----------------
__device__ __forceinline__ uint32_t smem_u32(const void* p) {
    uint32_t a;
    asm("{ .reg .u64 t; cvta.to.shared.u64 t, %1; cvt.u32.u64 %0, t; }"
        : "=r"(a) : "l"(p));
    return a;
}
__device__ __forceinline__ void cp16(uint32_t d, const void* s, bool v) {
    int sz = v ? 16 : 0;
    asm volatile("cp.async.cg.shared.global [%0], [%1], 16, %2;\n"
                 :: "r"(d), "l"(s), "r"(sz));
}
#define CP_COMMIT() asm volatile("cp.async.commit_group;\n")
#define CP_WAIT(n)  asm volatile("cp.async.wait_group %0;\n" :: "n"(n))

#define LDM4(r, addr) \
    asm volatile("ldmatrix.sync.aligned.m8n8.x4.shared.b16 {%0,%1,%2,%3}, [%4];" \
        : "=r"((r)[0]), "=r"((r)[1]), "=r"((r)[2]), "=r"((r)[3]) : "r"(addr))

#define MMA(d, a, b0, b1) \
    asm volatile("mma.sync.aligned.m16n8k16.row.col.f32.bf16.bf16.f32 " \
        "{%0,%1,%2,%3},{%4,%5,%6,%7},{%8,%9},{%0,%1,%2,%3};" \
        : "+f"((d)[0]), "+f"((d)[1]), "+f"((d)[2]), "+f"((d)[3]) \
        : "r"((a)[0]), "r"((a)[1]), "r"((a)[2]), "r"((a)[3]), "r"(b0), "r"(b1))

// release/acquire primitives for the dataflow counters
__device__ __forceinline__ unsigned ld_acq(const unsigned* p) {
    unsigned v;
    asm volatile("ld.acquire.gpu.global.u32 %0, [%1];" : "=r"(v) : "l"(p));
    return v;
}
__device__ __forceinline__ uint4 ld_acq4(const unsigned* p) {
    uint4 v;
    asm volatile("ld.acquire.gpu.global.v4.u32 {%0,%1,%2,%3}, [%4];"
        : "=r"(v.x), "=r"(v.y), "=r"(v.z), "=r"(v.w) : "l"(p));
    return v;
}
__device__ __forceinline__ void red_release(unsigned* p) {
    asm volatile("red.release.gpu.global.add.u32 [%0], 1;" :: "l"(p) : "memory");
}

// fast activations (clamped; rel err ~1e-6)
__device__ __forceinline__ float sigf(float x) {
    x = fminf(fmaxf(x, -30.0f), 30.0f);
    return __fdividef(1.0f, 1.0f + __expf(-x));
}
__device__ __forceinline__ float tanhfast(float x) {
    x = fminf(fmaxf(x, -15.0f), 15.0f);
    float e = __expf(2.0f * x);
    return __fdividef(e - 1.0f, e + 1.0f);
}

// ---------------- fused init (h state, counters) + weight hi/lo split ------
__global__ void initcvt_kernel(const float* __restrict__ in0, __nv_bfloat16* __restrict__ hi0,
                               __nv_bfloat16* __restrict__ lo0, int n0,
                               const float* __restrict__ in1, __nv_bfloat16* __restrict__ hi1,
                               __nv_bfloat16* __restrict__ lo1, int n1,
                               const float* __restrict__ in2, __nv_bfloat16* __restrict__ hi2,
                               __nv_bfloat16* __restrict__ lo2, int n2)
{
    int gid = blockIdx.x * blockDim.x + threadIdx.x;

    if (gid < 2 * BB * HH) {
        g_hbhi[gid / (BB * HH)][0][gid % (BB * HH)] = __float2bfloat16(0.0f);
        g_hblo[gid / (BB * HH)][0][gid % (BB * HH)] = __float2bfloat16(0.0f);
    }
    if (gid < 2 * SS * 4) (&g_bar[0][0][0])[gid] = 0u;

    int i = gid;
    const float* in; __nv_bfloat16 *hi, *lo;
    if (i < n0)                { in = in0; hi = hi0; lo = lo0; }
    else if (i < n0 + n1)      { i -= n0; in = in1; hi = hi1; lo = lo1; }
    else if (i < n0 + n1 + n2) { i -= n0 + n1; in = in2; hi = hi2; lo = lo2; }
    else return;
    float v = in[i];
    __nv_bfloat16 h = __float2bfloat16(v);
    hi[i] = h;
    lo[i] = __float2bfloat16(v - __bfloat162float(h));
}

// ---------------- segment mean pool (writes split bf16) ----------------
__global__ void pool_kernel(const float* __restrict__ f0,
                            const int*   __restrict__ counts,
                            __nv_bfloat16* __restrict__ xhi,
                            __nv_bfloat16* __restrict__ xlo)
{
    __shared__ int s_start[WW];
    __shared__ int s_cnt[WW];
    int b = blockIdx.x;
    int tid = threadIdx.x;
    if (tid == 0) {
        int run = 0;
        for (int j = 0; j < WW; ++j) {
            int c = counts[b * WW + j];
            s_start[j] = run; s_cnt[j] = c; run += c;
        }
    }
    __syncthreads();
    const float* fb = f0 + (size_t)b * SS * DD;
    __nv_bfloat16* xh = xhi + (size_t)b * SS * DD;
    __nv_bfloat16* xl = xlo + (size_t)b * SS * DD;
    for (int idx = tid; idx < WW * DD; idx += blockDim.x) {
        int j = idx / DD, d = idx - j * DD;
        int st = s_start[j], c = s_cnt[j];
        float v = 0.0f;
        for (int p = 0; p < c; ++p) v += fb[(size_t)(st + p) * DD + d];
        v /= (float)c;
        __nv_bfloat16 h = __float2bfloat16(v);
        xh[idx] = h;
        xl[idx] = __float2bfloat16(v - __bfloat162float(h));
    }
    for (int idx = tid; idx < (SS - WW) * DD; idx += blockDim.x) {
        float v = fb[WW * DD + idx];
        __nv_bfloat16 h = __float2bfloat16(v);
        xh[WW * DD + idx] = h;
        xl[WW * DD + idx] = __float2bfloat16(v - __bfloat162float(h));
    }
}

// ---------------- split-bf16 tensor-core GEMM (mma.sync) ----------------
// C = (Ahi+Alo)*(Bhi+Blo)^T + bias1 + bias2 ; 3 terms, fp32 accumulate.
// 128x128 tile, BK=32, 256 threads, 64x32 warp tiles.
// __launch_bounds__(256,2): cap regs at 128 so 2 CTAs co-reside per SM.
// tstore=0: C[m][n] row-major. tstore=1: C[(t*N+n)*64+b], tile covers 64b x 2t.
#define ARRB  (128 * 80)
#define STGB  (4 * ARRB)

__global__ void __launch_bounds__(256, 2)
gemm3_kernel(const __nv_bfloat16* __restrict__ Ahi, const __nv_bfloat16* __restrict__ Alo,
             const __nv_bfloat16* __restrict__ Bhi, const __nv_bfloat16* __restrict__ Blo,
             const float* __restrict__ bias1, const float* __restrict__ bias2,
             float* __restrict__ C, int N, int K, int tstore)
{
    extern __shared__ char smem[];
    uint32_t sb = smem_u32(smem);
    int tid = threadIdx.x, lane = tid & 31, wid = tid >> 5;
    int wm = wid >> 2, wn = wid & 3;
    int bm = blockIdx.y, bn = blockIdx.x;

    int lr = tid >> 1;
    int lc = (tid & 1) * 2;
    int arow = tstore ? ((lr & 63) * SS + bm * 2 + (lr >> 6))
                      : (bm * 128 + lr);
    int brow = bn * 128 + lr;
    bool bv  = brow < N;
    const __nv_bfloat16* pAh = Ahi + (size_t)arow * K;
    const __nv_bfloat16* pAl = Alo + (size_t)arow * K;
    const __nv_bfloat16* pBh = Bhi + (size_t)(bv ? brow : 0) * K;
    const __nv_bfloat16* pBl = Blo + (size_t)(bv ? brow : 0) * K;
    uint32_t sd = sb + lr * 80 + lc * 16;

    float acc[4][4][4];
#pragma unroll
    for (int a = 0; a < 4; ++a)
#pragma unroll
        for (int b = 0; b < 4; ++b)
#pragma unroll
            for (int c = 0; c < 4; ++c) acc[a][b][c] = 0.0f;

    int KT = K >> 5;

    {
        uint32_t d = sd;
#pragma unroll
        for (int cc = 0; cc < 2; ++cc) {
            cp16(d + cc * 16 + 0 * ARRB, pAh + (lc + cc) * 8, true);
            cp16(d + cc * 16 + 1 * ARRB, pAl + (lc + cc) * 8, true);
            cp16(d + cc * 16 + 2 * ARRB, pBh + (lc + cc) * 8, bv);
            cp16(d + cc * 16 + 3 * ARRB, pBl + (lc + cc) * 8, bv);
        }
        CP_COMMIT();
    }

    int la  = lane & 15, lc4 = lane >> 4;
    int lb  = (lane & 7) + ((lane & 16) >> 1);
    int lbc = (lane >> 3) & 1;

    for (int i = 0; i < KT; ++i) {
        CP_WAIT(0);
        __syncthreads();
        if (i + 1 < KT) {
            int ko = (i + 1) << 5;
            uint32_t d = sd + ((i + 1) & 1) * STGB;
#pragma unroll
            for (int cc = 0; cc < 2; ++cc) {
                cp16(d + cc * 16 + 0 * ARRB, pAh + ko + (lc + cc) * 8, true);
                cp16(d + cc * 16 + 1 * ARRB, pAl + ko + (lc + cc) * 8, true);
                cp16(d + cc * 16 + 2 * ARRB, pBh + ko + (lc + cc) * 8, bv);
                cp16(d + cc * 16 + 3 * ARRB, pBl + ko + (lc + cc) * 8, bv);
            }
            CP_COMMIT();
        }
        uint32_t st = sb + (i & 1) * STGB;
#pragma unroll
        for (int kh = 0; kh < 2; ++kh) {
            uint32_t aaddr = st + (wm * 64 + la) * 80 + (kh * 2 + lc4) * 16;
            uint32_t ah[4][4], al[4][4];
#pragma unroll
            for (int mt = 0; mt < 4; ++mt) {
                LDM4(ah[mt], aaddr + mt * 1280);
                LDM4(al[mt], aaddr + mt * 1280 + ARRB);
            }
            uint32_t bbase = st + 2 * ARRB + (wn * 32 + lb) * 80 + (kh * 2 + lbc) * 16;
            uint32_t bh[2][4], bl[2][4];
#pragma unroll
            for (int ntp = 0; ntp < 2; ++ntp) {
                LDM4(bh[ntp], bbase + ntp * 1280);
                LDM4(bl[ntp], bbase + ntp * 1280 + ARRB);
            }
#pragma unroll
            for (int mt = 0; mt < 4; ++mt)
#pragma unroll
                for (int ntp = 0; ntp < 2; ++ntp) {
                    MMA(acc[mt][2 * ntp + 0], ah[mt], bh[ntp][0], bh[ntp][1]);
                    MMA(acc[mt][2 * ntp + 1], ah[mt], bh[ntp][2], bh[ntp][3]);
                }
#pragma unroll
            for (int mt = 0; mt < 4; ++mt)
#pragma unroll
                for (int ntp = 0; ntp < 2; ++ntp) {
                    MMA(acc[mt][2 * ntp + 0], ah[mt], bl[ntp][0], bl[ntp][1]);
                    MMA(acc[mt][2 * ntp + 1], ah[mt], bl[ntp][2], bl[ntp][3]);
                }
#pragma unroll
            for (int mt = 0; mt < 4; ++mt)
#pragma unroll
                for (int ntp = 0; ntp < 2; ++ntp) {
                    MMA(acc[mt][2 * ntp + 0], al[mt], bh[ntp][0], bh[ntp][1]);
                    MMA(acc[mt][2 * ntp + 1], al[mt], bh[ntp][2], bh[ntp][3]);
                }
        }
        __syncthreads();
    }

    // epilogue
#pragma unroll
    for (int mt = 0; mt < 4; ++mt) {
        int r0_ = wm * 64 + mt * 16 + (lane >> 2);      // tile row 0..127
#pragma unroll
        for (int nt = 0; nt < 4; ++nt) {
            int n0 = bn * 128 + wn * 32 + nt * 8 + (lane & 3) * 2;
            float* a = acc[mt][nt];
            if (!tstore) {
                int m0 = bm * 128 + r0_;
                if (n0 < N) {
                    float bs = bias1[n0] + (bias2 ? bias2[n0] : 0.0f);
                    C[(size_t)m0 * N + n0]       = a[0] + bs;
                    C[(size_t)(m0 + 8) * N + n0] = a[2] + bs;
                }
                if (n0 + 1 < N) {
                    float bs = bias1[n0 + 1] + (bias2 ? bias2[n0 + 1] : 0.0f);
                    C[(size_t)m0 * N + n0 + 1]       = a[1] + bs;
                    C[(size_t)(m0 + 8) * N + n0 + 1] = a[3] + bs;
                }
            } else {
                int b_ = r0_ & 63;
                int t_ = bm * 2 + (r0_ >> 6);
                float bs0 = bias1[n0] + bias2[n0];
                float bs1 = bias1[n0 + 1] + bias2[n0 + 1];
                size_t o0 = ((size_t)t_ * N + n0) * 64 + b_;
                C[o0]          = a[0] + bs0;
                C[o0 + 64]     = a[1] + bs1;
                C[o0 + 8]      = a[2] + bs0;
                C[o0 + 64 + 8] = a[3] + bs1;
            }
        }
    }
}

// ---------------- persistent tensor-core LSTM recurrence ----------------
// Dataflow sync: chunk q of h (rows 96q..96q+95) is produced by CTAs
// 16q..16q+15 of the same direction. Producers red.release a per-step
// per-group counter after the h write; consumers ld.acquire-poll the group
// counter right before issuing that chunk's cp.async. No global barrier,
// no threadfence.
#define LA_HI   0
#define LA_LO   50176           // 64 rows * 784B pitch
#define LW_HI   100352
#define LW_LO   119168          // 24 rows * 784B
#define LGATES  137984          // 64 * 26 floats
#define LCS     144640          // 384 floats
#define LHSTH   146176          // 384 bf16 (h-hi stage)
#define LHSTL   146944          // 384 bf16 (h-lo stage)
#define LSMEM   147712
#define PITCH   784

__global__ void __launch_bounds__(RTH, 1)
lstm_kernel(const float* __restrict__ Whh_f, const float* __restrict__ Whh_b)
{
    extern __shared__ char smem[];
    uint32_t sb = smem_u32(smem);
    float* gates_s = (float*)(smem + LGATES);
    float* c_s     = (float*)(smem + LCS);

    int cta = blockIdx.x;
    int dir = (cta >= NCD) ? 1 : 0;
    int ci  = cta - dir * NCD;
    const float* Whh = dir ? Whh_b : Whh_f;
    const float* xp  = dir ? g_xptb : g_xptf;
    int n0  = ci * CH;
    int tid = threadIdx.x;
    int lane = tid & 31, wid = tid >> 5;
    int mt = wid & 3;          // m-tile (16 b rows)
    int nt = wid >> 2;         // n-tile (8 gate rows)
    int mygrp = ci >> 4;       // h-group this CTA produces into

    // ---- load + split Whh slice into SMEM (once) ----
    for (int idx = tid; idx < RR * HH; idx += RTH) {
        int r = idx / HH, k = idx - r * HH;
        int gi = r / CH, j = r - gi * CH;
        float v = Whh[(size_t)(gi * HH + n0 + j) * HH + k];
        __nv_bfloat16 h = __float2bfloat16(v);
        *(__nv_bfloat16*)(smem + LW_HI + r * PITCH + k * 2) = h;
        *(__nv_bfloat16*)(smem + LW_LO + r * PITCH + k * 2) =
            __float2bfloat16(v - __bfloat162float(h));
    }
    for (int idx = tid; idx < CH * BB; idx += RTH) c_s[idx] = 0.0f;
    __syncthreads();

    int cj = tid >> 6;         // 0..5
    int cb = tid & 63;

    int la  = lane & 15, lc4 = lane >> 4;
    uint32_t aAddrBase = sb + LA_HI + (mt * 16 + la) * PITCH + lc4 * 16;
    uint32_t bAddrBase = sb + LW_HI + ((lane >= 16) ? (LW_LO - LW_HI) : 0u)
                       + (nt * 8 + (lane & 7)) * PITCH + ((lane >> 3) & 1) * 16;

    // initial xp prefetch (transposed layout: [t][feat][b], lanes contiguous)
    float xg[4];
    {
        int t0 = dir ? (SS - 1) : 0;
        const float* xr = xp + ((size_t)t0 * FOURH + n0 + cj) * 64 + cb;
#pragma unroll
        for (int gi = 0; gi < 4; ++gi) xg[gi] = __ldg(xr + (size_t)gi * HH * 64);
    }

    for (int s = 0; s < SS; ++s) {
        int t = dir ? (SS - 1 - s) : s;
        int p = s & 1;
        int np = (s + 1) & 1;

        const char* srcH = (const char*)&g_hbhi[dir][p][0];
        const char* srcL = (const char*)&g_hblo[dir][p][0];

        // one acquire vector load covers the common all-ready case
        uint4 cnt = make_uint4(16u, 16u, 16u, 16u);
        if (s > 0) cnt = ld_acq4(&g_bar[dir][s - 1][0]);

#pragma unroll
        for (int q = 0; q < 4; ++q) {
            unsigned have = (q == 0) ? cnt.x : (q == 1) ? cnt.y
                          : (q == 2) ? cnt.z : cnt.w;
            if (have < 16u) {
                const unsigned* cp_ = &g_bar[dir][s - 1][q];
                do { have = ld_acq(cp_); } while (have < 16u);
            }
#pragma unroll
            for (int i = 0; i < 2; ++i) {
                int e = i * RTH + tid;            // 0..767
                int row = e / 12, cc = e - row * 12;
                uint32_t so = row * 768 + q * 192 + cc * 16;
                uint32_t doff = row * PITCH + q * 192 + cc * 16;
                cp16(sb + LA_HI + doff, srcH + so, true);
                cp16(sb + LA_LO + doff, srcL + so, true);
            }
            CP_COMMIT();
        }

        float acc[4] = {0.f, 0.f, 0.f, 0.f};
#pragma unroll
        for (int q = 0; q < 4; ++q) {
            if      (q == 0) CP_WAIT(3);
            else if (q == 1) CP_WAIT(2);
            else if (q == 2) CP_WAIT(1);
            else             CP_WAIT(0);
            __syncthreads();
#pragma unroll
            for (int kk = 0; kk < 6; ++kk) {
                int k16 = q * 6 + kk;
                uint32_t ka = aAddrBase + k16 * 32;
                uint32_t kb = bAddrBase + k16 * 32;
                uint32_t ah[4], al[4], bb[4];
                LDM4(ah, ka);
                LDM4(al, ka + (LA_LO - LA_HI));
                LDM4(bb, kb);                      // bb = {bh0, bh1, bl0, bl1}
                MMA(acc, ah, bb[0], bb[1]);
                MMA(acc, ah, bb[2], bb[3]);
                MMA(acc, al, bb[0], bb[1]);
            }
        }

        {
            int brow = mt * 16 + (lane >> 2);
            int rcol = nt * 8 + (lane & 3) * 2;
            *(float2*)&gates_s[brow * 26 + rcol]       = make_float2(acc[0], acc[1]);
            *(float2*)&gates_s[(brow + 8) * 26 + rcol] = make_float2(acc[2], acc[3]);
        }
        __syncthreads();

        // ---- cell update (1 cell per thread) ----
        {
            float ig = gates_s[cb * 26 + 0 * CH + cj] + xg[0];
            float fg = gates_s[cb * 26 + 1 * CH + cj] + xg[1];
            float gg = gates_s[cb * 26 + 2 * CH + cj] + xg[2];
            float og = gates_s[cb * 26 + 3 * CH + cj] + xg[3];
            float c  = c_s[tid];
            c = sigf(fg) * c + sigf(ig) * tanhfast(gg);
            float h = sigf(og) * tanhfast(c);
            c_s[tid] = c;
            __nv_bfloat16 hh = __float2bfloat16(h);
            __nv_bfloat16 hl = __float2bfloat16(h - __bfloat162float(hh));
            ((__nv_bfloat16*)(smem + LHSTH))[cb * CH + cj] = hh;
            ((__nv_bfloat16*)(smem + LHSTL))[cb * CH + cj] = hl;
            size_t fo = ((size_t)t * K2H + dir * HH + n0 + cj) * 64 + cb;
            g_f1thi[fo] = hh;
            g_f1tlo[fo] = hl;
        }

        // ---- prefetch xp for next step ----
        if (s + 1 < SS) {
            int t1 = dir ? (SS - 2 - s) : (s + 1);
            const float* xr = xp + ((size_t)t1 * FOURH + n0 + cj) * 64 + cb;
#pragma unroll
            for (int gi = 0; gi < 4; ++gi) xg[gi] = __ldg(xr + (size_t)gi * HH * 64);
        }

        __syncthreads();   // h stage visible

        // ---- cooperative h write: 12B contiguous run per (comp, b) ----
        if (tid < 128) {
            int b = tid & 63;
            int comp = tid >> 6;
            const uint32_t* s3 = (const uint32_t*)(smem + (comp ? LHSTL : LHSTH) + b * 12);
            __nv_bfloat16* gdst = (comp ? &g_hblo[dir][np][0] : &g_hbhi[dir][np][0])
                                  + b * HH + n0;
            uint32_t w0 = s3[0], w1 = s3[1], w2 = s3[2];
            ((uint32_t*)gdst)[0] = w0;
            ((uint32_t*)gdst)[1] = w1;
            ((uint32_t*)gdst)[2] = w2;
        }

        // ---- arrive: release-add on this CTA's group counter ----
        __syncthreads();
        if (tid == 0) red_release(&g_bar[dir][s][mygrp]);
    }
}

// ---------------- f1t [t][feat][b] -> f1 [b][t][feat] transpose ----------------
__global__ void tr_kernel()
{
    __shared__ unsigned short tile2[64][66];   // [b][i-within-tile]
    const int R = SS * K2H;                    // 393216
    const __nv_bfloat16* src = blockIdx.z ? g_f1tlo : g_f1thi;
    __nv_bfloat16*       dst = blockIdx.z ? g_f1lo  : g_f1hi;
    int i0 = blockIdx.x * 64;
    int tid = threadIdx.x;

#pragma unroll
    for (int ph = 0; ph < 8; ++ph) {
        int idx = ph * 256 + tid;
        int r  = idx >> 5;
        int cl = idx & 31;
        uint32_t w = *(const uint32_t*)(src + (size_t)(i0 + r) * 64 + cl * 2);
        tile2[cl * 2 + 0][r] = (unsigned short)(w & 0xffffu);
        tile2[cl * 2 + 1][r] = (unsigned short)(w >> 16);
    }
    __syncthreads();

#pragma unroll
    for (int ph = 0; ph < 8; ++ph) {
        int idx = ph * 256 + tid;
        int b  = idx >> 5;
        int cl = idx & 31;
        uint32_t w = *(const uint32_t*)&tile2[b][cl * 2];
        *(uint32_t*)(dst + (size_t)b * R + i0 + cl * 2) = w;
    }
}

// ---------------- launcher ----------------
extern "C" void kernel_launch(void* const* d_in, const int* in_sizes, int n_in,
                              void* d_out, int out_size)
{
    const float* f0     = (const float*)d_in[0];
    const int*   counts = (const int*)  d_in[1];
    const float* Wih_f  = (const float*)d_in[2];
    const float* Whh_f  = (const float*)d_in[3];
    const float* bih_f  = (const float*)d_in[4];
    const float* bhh_f  = (const float*)d_in[5];
    const float* Wih_b  = (const float*)d_in[6];
    const float* Whh_b  = (const float*)d_in[7];
    const float* bih_b  = (const float*)d_in[8];
    const float* bhh_b  = (const float*)d_in[9];
    const float* Wlin   = (const float*)d_in[10];
    const float* blin   = (const float*)d_in[11];
    float* out = (float*)d_out;

    void* p;
    cudaGetSymbolAddress(&p, g_xhi);     __nv_bfloat16* xhi = (__nv_bfloat16*)p;
    cudaGetSymbolAddress(&p, g_xlo);     __nv_bfloat16* xlo = (__nv_bfloat16*)p;
    cudaGetSymbolAddress(&p, g_xptf);    float* gxptf = (float*)p;
    cudaGetSymbolAddress(&p, g_xptb);    float* gxptb = (float*)p;
    cudaGetSymbolAddress(&p, g_f1hi);    __nv_bfloat16* f1hi = (__nv_bfloat16*)p;
    cudaGetSymbolAddress(&p, g_f1lo);    __nv_bfloat16* f1lo = (__nv_bfloat16*)p;
    cudaGetSymbolAddress(&p, g_wihf_hi); __nv_bfloat16* wfh = (__nv_bfloat16*)p;
    cudaGetSymbolAddress(&p, g_wihf_lo); __nv_bfloat16* wfl = (__nv_bfloat16*)p;
    cudaGetSymbolAddress(&p, g_wihb_hi); __nv_bfloat16* wbh = (__nv_bfloat16*)p;
    cudaGetSymbolAddress(&p, g_wihb_lo); __nv_bfloat16* wbl = (__nv_bfloat16*)p;
    cudaGetSymbolAddress(&p, g_wlin_hi); __nv_bfloat16* wlh = (__nv_bfloat16*)p;
    cudaGetSymbolAddress(&p, g_wlin_lo); __nv_bfloat16* wll = (__nv_bfloat16*)p;

    cudaFuncSetAttribute(lstm_kernel, cudaFuncAttributeMaxDynamicSharedMemorySize, LSMEM);
    cudaFuncSetAttribute(gemm3_kernel, cudaFuncAttributeMaxDynamicSharedMemorySize, 2 * STGB);

    int nw = FOURH * DD;
    int nl = CC * K2H;
    int ncvt = 2 * nw + nl;
    initcvt_kernel<<<(ncvt + 255) / 256, 256>>>(Wih_f, wfh, wfl, nw,
                                                Wih_b, wbh, wbl, nw,
                                                Wlin,  wlh, wll, nl);
    pool_kernel<<<BB, 256>>>(f0, counts, xhi, xlo);

    dim3 gproj(FOURH / 128, MM / 128);   // 12 x 256
    gemm3_kernel<<<gproj, 256, 2 * STGB>>>(xhi, xlo, wfh, wfl, bih_f, bhh_f,
                                           gxptf, FOURH, DD, 1);
    gemm3_kernel<<<gproj, 256, 2 * STGB>>>(xhi, xlo, wbh, wbl, bih_b, bhh_b,
                                           gxptb, FOURH, DD, 1);

    lstm_kernel<<<2 * NCD, RTH, LSMEM>>>(Whh_f, Whh_b);

    dim3 gtr(SS * K2H / 64, 1, 2);       // 6144 x 1 x 2
    tr_kernel<<<gtr, 256>>>();

    dim3 gout((CC + 127) / 128, MM / 128);  // 4 x 256
    gemm3_kernel<<<gout, 256, 2 * STGB>>>(f1hi, f1lo, wlh, wll, blin, nullptr,
                                          out, CC, K2H, 0);
}

// round 15
// speedup vs baseline: 2.0166x; 1.1327x over previous
#include <cuda_runtime.h>
#include <cuda_bf16.h>
#include <math.h>
#include <stdint.h>

// Problem dims
#define BB   64
#define SS   512
#define DD   768
#define WW   256
#define HH   384
#define FOURH 1536
#define CC   425
#define K2H  768
#define MM   (BB*SS)      // 32768 rows

// Recurrence config: 2 dirs x 4 batch-groups x 16 h-groups = 128 CTAs
#define NCD   64          // CTAs per direction
#define NBG   4           // batch groups (16 batches each)
#define CB    16          // batches per CTA
#define NJ    24          // h-indices per CTA
#define GR    96          // gate rows per CTA (4 gates * NJ)
#define RTH   384         // 12 warps, each owns one n8 tile of [16 x 96]

// -------- scratch (device globals; no allocation allowed) --------
__device__ __nv_bfloat16 g_xhi[MM * DD];
__device__ __nv_bfloat16 g_xlo[MM * DD];
__device__ float g_xptf[MM * FOURH];              // proj fwd, layout [t][feat][b]
__device__ float g_xptb[MM * FOURH];              // proj bwd, layout [t][feat][b]
__device__ __nv_bfloat16 g_f1thi[MM * K2H];       // [t][feat][b]
__device__ __nv_bfloat16 g_f1tlo[MM * K2H];
__device__ __nv_bfloat16 g_f1hi[MM * K2H];        // [b][t][feat] (post-transpose)
__device__ __nv_bfloat16 g_f1lo[MM * K2H];
__device__ __nv_bfloat16 g_hbhi[2][2][BB * HH];   // [dir][parity][b*384+k]
__device__ __nv_bfloat16 g_hblo[2][2][BB * HH];
__device__ unsigned g_bar[2][SS][NBG][4];         // per-step/bg/chunk counters (4 producers)
__device__ __nv_bfloat16 g_wihf_hi[FOURH * DD], g_wihf_lo[FOURH * DD];
__device__ __nv_bfloat16 g_wihb_hi[FOURH * DD], g_wihb_lo[FOURH * DD];
__device__ __nv_bfloat16 g_wlin_hi[CC * K2H],  g_wlin_lo[CC * K2H];

// ---------------- small helpers ----------------
__device__ __forceinline__ uint32_t smem_u32(const void* p) {
    uint32_t a;
    asm("{ .reg .u64 t; cvta.to.shared.u64 t, %1; cvt.u32.u64 %0, t; }"
        : "=r"(a) : "l"(p));
    return a;
}
__device__ __forceinline__ void cp16(uint32_t d, const void* s, bool v) {
    int sz = v ? 16 : 0;
    asm volatile("cp.async.cg.shared.global [%0], [%1], 16, %2;\n"
                 :: "r"(d), "l"(s), "r"(sz));
}
#define CP_COMMIT() asm volatile("cp.async.commit_group;\n")
#define CP_WAIT(n)  asm volatile("cp.async.wait_group %0;\n" :: "n"(n))

#define LDM4(r, addr) \
    asm volatile("ldmatrix.sync.aligned.m8n8.x4.shared.b16 {%0,%1,%2,%3}, [%4];" \
        : "=r"((r)[0]), "=r"((r)[1]), "=r"((r)[2]), "=r"((r)[3]) : "r"(addr))

#define MMA(d, a, b0, b1) \
    asm volatile("mma.sync.aligned.m16n8k16.row.col.f32.bf16.bf16.f32 " \
        "{%0,%1,%2,%3},{%4,%5,%6,%7},{%8,%9},{%0,%1,%2,%3};" \
        : "+f"((d)[0]), "+f"((d)[1]), "+f"((d)[2]), "+f"((d)[3]) \
        : "r"((a)[0]), "r"((a)[1]), "r"((a)[2]), "r"((a)[3]), "r"(b0), "r"(b1))

// release/acquire primitives for the dataflow counters
__device__ __forceinline__ unsigned ld_acq(const unsigned* p) {
    unsigned v;
    asm volatile("ld.acquire.gpu.global.u32 %0, [%1];" : "=r"(v) : "l"(p));
    return v;
}
__device__ __forceinline__ uint4 ld_acq4(const unsigned* p) {
    uint4 v;
    asm volatile("ld.acquire.gpu.global.v4.u32 {%0,%1,%2,%3}, [%4];"
        : "=r"(v.x), "=r"(v.y), "=r"(v.z), "=r"(v.w) : "l"(p));
    return v;
}
__device__ __forceinline__ void red_release(unsigned* p) {
    asm volatile("red.release.gpu.global.add.u32 [%0], 1;" :: "l"(p) : "memory");
}

// fast activations (clamped; rel err ~1e-6)
__device__ __forceinline__ float sigf(float x) {
    x = fminf(fmaxf(x, -30.0f), 30.0f);
    return __fdividef(1.0f, 1.0f + __expf(-x));
}
__device__ __forceinline__ float tanhfast(float x) {
    x = fminf(fmaxf(x, -15.0f), 15.0f);
    float e = __expf(2.0f * x);
    return __fdividef(e - 1.0f, e + 1.0f);
}

// ---------------- fused init (h state, counters) + weight hi/lo split ------
__global__ void initcvt_kernel(const float* __restrict__ in0, __nv_bfloat16* __restrict__ hi0,
                               __nv_bfloat16* __restrict__ lo0, int n0,
                               const float* __restrict__ in1, __nv_bfloat16* __restrict__ hi1,
                               __nv_bfloat16* __restrict__ lo1, int n1,
                               const float* __restrict__ in2, __nv_bfloat16* __restrict__ hi2,
                               __nv_bfloat16* __restrict__ lo2, int n2)
{
    int gid = blockIdx.x * blockDim.x + threadIdx.x;

    if (gid < 2 * BB * HH) {
        g_hbhi[gid / (BB * HH)][0][gid % (BB * HH)] = __float2bfloat16(0.0f);
        g_hblo[gid / (BB * HH)][0][gid % (BB * HH)] = __float2bfloat16(0.0f);
    }
    if (gid < 2 * SS * NBG * 4) (&g_bar[0][0][0][0])[gid] = 0u;

    int i = gid;
    const float* in; __nv_bfloat16 *hi, *lo;
    if (i < n0)                { in = in0; hi = hi0; lo = lo0; }
    else if (i < n0 + n1)      { i -= n0; in = in1; hi = hi1; lo = lo1; }
    else if (i < n0 + n1 + n2) { i -= n0 + n1; in = in2; hi = hi2; lo = lo2; }
    else return;
    float v = in[i];
    __nv_bfloat16 h = __float2bfloat16(v);
    hi[i] = h;
    lo[i] = __float2bfloat16(v - __bfloat162float(h));
}

// ---------------- segment mean pool (writes split bf16) ----------------
__global__ void pool_kernel(const float* __restrict__ f0,
                            const int*   __restrict__ counts,
                            __nv_bfloat16* __restrict__ xhi,
                            __nv_bfloat16* __restrict__ xlo)
{
    __shared__ int s_start[WW];
    __shared__ int s_cnt[WW];
    int b = blockIdx.x;
    int tid = threadIdx.x;
    if (tid == 0) {
        int run = 0;
        for (int j = 0; j < WW; ++j) {
            int c = counts[b * WW + j];
            s_start[j] = run; s_cnt[j] = c; run += c;
        }
    }
    __syncthreads();
    const float* fb = f0 + (size_t)b * SS * DD;
    __nv_bfloat16* xh = xhi + (size_t)b * SS * DD;
    __nv_bfloat16* xl = xlo + (size_t)b * SS * DD;
    for (int idx = tid; idx < WW * DD; idx += blockDim.x) {
        int j = idx / DD, d = idx - j * DD;
        int st = s_start[j], c = s_cnt[j];
        float v = 0.0f;
        for (int p = 0; p < c; ++p) v += fb[(size_t)(st + p) * DD + d];
        v /= (float)c;
        __nv_bfloat16 h = __float2bfloat16(v);
        xh[idx] = h;
        xl[idx] = __float2bfloat16(v - __bfloat162float(h));
    }
    for (int idx = tid; idx < (SS - WW) * DD; idx += blockDim.x) {
        float v = fb[WW * DD + idx];
        __nv_bfloat16 h = __float2bfloat16(v);
        xh[WW * DD + idx] = h;
        xl[WW * DD + idx] = __float2bfloat16(v - __bfloat162float(h));
    }
}

// ---------------- split-bf16 tensor-core GEMM (mma.sync) ----------------
// Unchanged from round 14 (683us/launch, tensor 55.8%, occ 24.4%).
#define ARRB  (128 * 80)
#define STGB  (4 * ARRB)

__global__ void __launch_bounds__(256, 2)
gemm3_kernel(const __nv_bfloat16* __restrict__ Ahi, const __nv_bfloat16* __restrict__ Alo,
             const __nv_bfloat16* __restrict__ Bhi, const __nv_bfloat16* __restrict__ Blo,
             const float* __restrict__ bias1, const float* __restrict__ bias2,
             float* __restrict__ C, int N, int K, int tstore)
{
    extern __shared__ char smem[];
    uint32_t sb = smem_u32(smem);
    int tid = threadIdx.x, lane = tid & 31, wid = tid >> 5;
    int wm = wid >> 2, wn = wid & 3;
    int bm = blockIdx.y, bn = blockIdx.x;

    int lr = tid >> 1;
    int lc = (tid & 1) * 2;
    int arow = tstore ? ((lr & 63) * SS + bm * 2 + (lr >> 6))
                      : (bm * 128 + lr);
    int brow = bn * 128 + lr;
    bool bv  = brow < N;
    const __nv_bfloat16* pAh = Ahi + (size_t)arow * K;
    const __nv_bfloat16* pAl = Alo + (size_t)arow * K;
    const __nv_bfloat16* pBh = Bhi + (size_t)(bv ? brow : 0) * K;
    const __nv_bfloat16* pBl = Blo + (size_t)(bv ? brow : 0) * K;
    uint32_t sd = sb + lr * 80 + lc * 16;

    float acc[4][4][4];
#pragma unroll
    for (int a = 0; a < 4; ++a)
#pragma unroll
        for (int b = 0; b < 4; ++b)
#pragma unroll
            for (int c = 0; c < 4; ++c) acc[a][b][c] = 0.0f;

    int KT = K >> 5;

    {
        uint32_t d = sd;
#pragma unroll
        for (int cc = 0; cc < 2; ++cc) {
            cp16(d + cc * 16 + 0 * ARRB, pAh + (lc + cc) * 8, true);
            cp16(d + cc * 16 + 1 * ARRB, pAl + (lc + cc) * 8, true);
            cp16(d + cc * 16 + 2 * ARRB, pBh + (lc + cc) * 8, bv);
            cp16(d + cc * 16 + 3 * ARRB, pBl + (lc + cc) * 8, bv);
        }
        CP_COMMIT();
    }

    int la  = lane & 15, lc4 = lane >> 4;
    int lb  = (lane & 7) + ((lane & 16) >> 1);
    int lbc = (lane >> 3) & 1;

    for (int i = 0; i < KT; ++i) {
        CP_WAIT(0);
        __syncthreads();
        if (i + 1 < KT) {
            int ko = (i + 1) << 5;
            uint32_t d = sd + ((i + 1) & 1) * STGB;
#pragma unroll
            for (int cc = 0; cc < 2; ++cc) {
                cp16(d + cc * 16 + 0 * ARRB, pAh + ko + (lc + cc) * 8, true);
                cp16(d + cc * 16 + 1 * ARRB, pAl + ko + (lc + cc) * 8, true);
                cp16(d + cc * 16 + 2 * ARRB, pBh + ko + (lc + cc) * 8, bv);
                cp16(d + cc * 16 + 3 * ARRB, pBl + ko + (lc + cc) * 8, bv);
            }
            CP_COMMIT();
        }
        uint32_t st = sb + (i & 1) * STGB;
#pragma unroll
        for (int kh = 0; kh < 2; ++kh) {
            uint32_t aaddr = st + (wm * 64 + la) * 80 + (kh * 2 + lc4) * 16;
            uint32_t ah[4][4], al[4][4];
#pragma unroll
            for (int mt = 0; mt < 4; ++mt) {
                LDM4(ah[mt], aaddr + mt * 1280);
                LDM4(al[mt], aaddr + mt * 1280 + ARRB);
            }
            uint32_t bbase = st + 2 * ARRB + (wn * 32 + lb) * 80 + (kh * 2 + lbc) * 16;
            uint32_t bh[2][4], bl[2][4];
#pragma unroll
            for (int ntp = 0; ntp < 2; ++ntp) {
                LDM4(bh[ntp], bbase + ntp * 1280);
                LDM4(bl[ntp], bbase + ntp * 1280 + ARRB);
            }
#pragma unroll
            for (int mt = 0; mt < 4; ++mt)
#pragma unroll
                for (int ntp = 0; ntp < 2; ++ntp) {
                    MMA(acc[mt][2 * ntp + 0], ah[mt], bh[ntp][0], bh[ntp][1]);
                    MMA(acc[mt][2 * ntp + 1], ah[mt], bh[ntp][2], bh[ntp][3]);
                }
#pragma unroll
            for (int mt = 0; mt < 4; ++mt)
#pragma unroll
                for (int ntp = 0; ntp < 2; ++ntp) {
                    MMA(acc[mt][2 * ntp + 0], ah[mt], bl[ntp][0], bl[ntp][1]);
                    MMA(acc[mt][2 * ntp + 1], ah[mt], bl[ntp][2], bl[ntp][3]);
                }
#pragma unroll
            for (int mt = 0; mt < 4; ++mt)
#pragma unroll
                for (int ntp = 0; ntp < 2; ++ntp) {
                    MMA(acc[mt][2 * ntp + 0], al[mt], bh[ntp][0], bh[ntp][1]);
                    MMA(acc[mt][2 * ntp + 1], al[mt], bh[ntp][2], bh[ntp][3]);
                }
        }
        __syncthreads();
    }

    // epilogue
#pragma unroll
    for (int mt = 0; mt < 4; ++mt) {
        int r0_ = wm * 64 + mt * 16 + (lane >> 2);      // tile row 0..127
#pragma unroll
        for (int nt = 0; nt < 4; ++nt) {
            int n0 = bn * 128 + wn * 32 + nt * 8 + (lane & 3) * 2;
            float* a = acc[mt][nt];
            if (!tstore) {
                int m0 = bm * 128 + r0_;
                if (n0 < N) {
                    float bs = bias1[n0] + (bias2 ? bias2[n0] : 0.0f);
                    C[(size_t)m0 * N + n0]       = a[0] + bs;
                    C[(size_t)(m0 + 8) * N + n0] = a[2] + bs;
                }
                if (n0 + 1 < N) {
                    float bs = bias1[n0 + 1] + (bias2 ? bias2[n0 + 1] : 0.0f);
                    C[(size_t)m0 * N + n0 + 1]       = a[1] + bs;
                    C[(size_t)(m0 + 8) * N + n0 + 1] = a[3] + bs;
                }
            } else {
                int b_ = r0_ & 63;
                int t_ = bm * 2 + (r0_ >> 6);
                float bs0 = bias1[n0] + bias2[n0];
                float bs1 = bias1[n0 + 1] + bias2[n0 + 1];
                size_t o0 = ((size_t)t_ * N + n0) * 64 + b_;
                C[o0]          = a[0] + bs0;
                C[o0 + 64]     = a[1] + bs1;
                C[o0 + 8]      = a[2] + bs0;
                C[o0 + 64 + 8] = a[3] + bs1;
            }
        }
    }
}

// ---------------- persistent tensor-core LSTM recurrence (2-D partition) ---
// CTA (dir, bg, hg): computes gates [16 batches x 96 gate rows] from
// h[16 batches x 384]. h copy per CTA per step: 24KB (vs 96KB for 1-D).
// Sync: counter per (dir, step, bg, k-chunk); producers = 4 CTAs (bg, hg in
// chunk), consumers = same-bg CTAs only.
#define PITCH   784
#define LA_HI   0                         // 16 rows * 784
#define LA_LO   12544
#define LW_HI   25088                     // 96 rows * 784
#define LW_LO   100352
#define LGATES  175616                    // 16 * 98 floats
#define LCS     181888                    // 384 floats
#define LHSTH   183424                    // 384 bf16
#define LHSTL   184192
#define LSMEM   184960
#define GPITCH  98

__global__ void __launch_bounds__(RTH, 1)
lstm_kernel(const float* __restrict__ Whh_f, const float* __restrict__ Whh_b)
{
    extern __shared__ char smem[];
    uint32_t sb = smem_u32(smem);
    float* gates_s = (float*)(smem + LGATES);
    float* c_s     = (float*)(smem + LCS);

    int cta = blockIdx.x;
    int dir = (cta >= NCD) ? 1 : 0;
    int ci  = cta - dir * NCD;
    int bg  = ci >> 4;                 // 0..3  batch group
    int hg  = ci & 15;                 // 0..15 h group
    const float* Whh = dir ? Whh_b : Whh_f;
    const float* xp  = dir ? g_xptb : g_xptf;
    int tid = threadIdx.x;
    int lane = tid & 31, wid = tid >> 5;
    int nt = wid;                      // each warp owns one n8 tile of 96 rows

    // ---- load + split Whh slice (96 rows x 384) into SMEM (once) ----
    for (int idx = tid; idx < GR * HH; idx += RTH) {
        int r = idx / HH, k = idx - r * HH;
        int gi = r / NJ, lj = r - gi * NJ;
        float v = Whh[(size_t)(gi * HH + hg * NJ + lj) * HH + k];
        __nv_bfloat16 h = __float2bfloat16(v);
        *(__nv_bfloat16*)(smem + LW_HI + r * PITCH + k * 2) = h;
        *(__nv_bfloat16*)(smem + LW_LO + r * PITCH + k * 2) =
            __float2bfloat16(v - __bfloat162float(h));
    }
    c_s[tid] = 0.0f;
    __syncthreads();

    // cell mapping: thread -> (batch b, local h-index lj)
    int cb_ = tid & 15;                // 0..15
    int lj  = tid >> 4;                // 0..23

    // ldmatrix addresses
    int la  = lane & 15, lc4 = lane >> 4;
    uint32_t aAddrBase = sb + LA_HI + la * PITCH + lc4 * 16;
    uint32_t bAddrBase = sb + LW_HI + ((lane >= 16) ? (LW_LO - LW_HI) : 0u)
                       + (nt * 8 + (lane & 7)) * PITCH + ((lane >> 3) & 1) * 16;

    // copy mapping: thread -> (comp hi/lo, row 0..15, 16B chunk 0..11)
    int ccomp = tid / 192;
    int crr   = tid - ccomp * 192;
    int crow  = crr / 12;
    int ccc   = crr - crow * 12;
    uint32_t cdst = sb + (ccomp ? LA_LO : LA_HI) + crow * PITCH + ccc * 16;
    int csrcoff = crow * 768 + ccc * 16;         // within the bg's 16-row slab

    // xp prefetch (transposed [t][feat][b]; feat = gi*384 + hg*24 + lj)
    float xg[4];
    {
        int t0 = dir ? (SS - 1) : 0;
        const float* xr = xp + ((size_t)t0 * FOURH + hg * NJ + lj) * 64 + bg * CB + cb_;
#pragma unroll
        for (int gi = 0; gi < 4; ++gi) xg[gi] = __ldg(xr + (size_t)gi * HH * 64);
    }

    for (int s = 0; s < SS; ++s) {
        int t = dir ? (SS - 1 - s) : s;
        int p = s & 1;
        int np = (s + 1) & 1;

        const char* srcH = (const char*)&g_hbhi[dir][p][0] + bg * CB * HH * 2;
        const char* srcL = (const char*)&g_hblo[dir][p][0] + bg * CB * HH * 2;

        // chunk readiness: counter[dir][s-1][bg][q] reaches 4
        uint4 cnt = make_uint4(4u, 4u, 4u, 4u);
        if (s > 0) cnt = ld_acq4(&g_bar[dir][s - 1][bg][0]);

#pragma unroll
        for (int q = 0; q < 4; ++q) {
            unsigned have = (q == 0) ? cnt.x : (q == 1) ? cnt.y
                          : (q == 2) ? cnt.z : cnt.w;
            if (have < 4u) {
                const unsigned* cp_ = &g_bar[dir][s - 1][bg][q];
                do { have = ld_acq(cp_); } while (have < 4u);
            }
            // copy chunk q: k-bytes [192q, 192q+192) of 16 rows, hi+lo
            cp16(cdst + q * 192, (ccomp ? srcL : srcH) + csrcoff + q * 192, true);
            CP_COMMIT();
        }

        // gate GEMM: 24 k16 steps in 4 chunks
        float acc[4] = {0.f, 0.f, 0.f, 0.f};
#pragma unroll
        for (int q = 0; q < 4; ++q) {
            if      (q == 0) CP_WAIT(3);
            else if (q == 1) CP_WAIT(2);
            else if (q == 2) CP_WAIT(1);
            else             CP_WAIT(0);
            __syncthreads();
#pragma unroll
            for (int kk = 0; kk < 6; ++kk) {
                int k16 = q * 6 + kk;
                uint32_t ka = aAddrBase + k16 * 32;
                uint32_t kb = bAddrBase + k16 * 32;
                uint32_t ah[4], al[4], bb[4];
                LDM4(ah, ka);
                LDM4(al, ka + (LA_LO - LA_HI));
                LDM4(bb, kb);                      // {bh0, bh1, bl0, bl1}
                MMA(acc, ah, bb[0], bb[1]);
                MMA(acc, ah, bb[2], bb[3]);
                MMA(acc, al, bb[0], bb[1]);
            }
        }

        // epilogue: gates [b][r], pitch 98 floats
        {
            int brow = lane >> 2;
            int rcol = nt * 8 + (lane & 3) * 2;
            *(float2*)&gates_s[brow * GPITCH + rcol]       = make_float2(acc[0], acc[1]);
            *(float2*)&gates_s[(brow + 8) * GPITCH + rcol] = make_float2(acc[2], acc[3]);
        }
        __syncthreads();

        // cell update (1 cell per thread: batch cb_, local h lj)
        {
            float ig = gates_s[cb_ * GPITCH + 0 * NJ + lj] + xg[0];
            float fg = gates_s[cb_ * GPITCH + 1 * NJ + lj] + xg[1];
            float gg = gates_s[cb_ * GPITCH + 2 * NJ + lj] + xg[2];
            float og = gates_s[cb_ * GPITCH + 3 * NJ + lj] + xg[3];
            float c  = c_s[tid];
            c = sigf(fg) * c + sigf(ig) * tanhfast(gg);
            float h = sigf(og) * tanhfast(c);
            c_s[tid] = c;
            __nv_bfloat16 hh = __float2bfloat16(h);
            __nv_bfloat16 hl = __float2bfloat16(h - __bfloat162float(hh));
            ((__nv_bfloat16*)(smem + LHSTH))[cb_ * NJ + lj] = hh;
            ((__nv_bfloat16*)(smem + LHSTL))[cb_ * NJ + lj] = hl;
            size_t fo = ((size_t)t * K2H + dir * HH + hg * NJ + lj) * 64 + bg * CB + cb_;
            g_f1thi[fo] = hh;
            g_f1tlo[fo] = hl;
        }

        // prefetch xp for next step
        if (s + 1 < SS) {
            int t1 = dir ? (SS - 2 - s) : (s + 1);
            const float* xr = xp + ((size_t)t1 * FOURH + hg * NJ + lj) * 64 + bg * CB + cb_;
#pragma unroll
            for (int gi = 0; gi < 4; ++gi) xg[gi] = __ldg(xr + (size_t)gi * HH * 64);
        }

        __syncthreads();   // h stage visible

        // cooperative h write: 48B (12 u32) per (comp, batch)
        {
            int comp = tid / 192;
            int rr   = tid - comp * 192;
            int b    = rr / 12;
            int w    = rr - b * 12;
            const uint32_t* ssrc = (const uint32_t*)(smem + (comp ? LHSTL : LHSTH) + b * NJ * 2);
            __nv_bfloat16* gdst = (comp ? &g_hblo[dir][np][0] : &g_hbhi[dir][np][0])
                                  + (bg * CB + b) * HH + hg * NJ;
            ((uint32_t*)gdst)[w] = ssrc[w];
        }

        // arrive: release-add on this CTA's (bg, chunk) counter
        __syncthreads();
        if (tid == 0) red_release(&g_bar[dir][s][bg][hg >> 2]);
    }
}

// ---------------- f1t [t][feat][b] -> f1 [b][t][feat] transpose ----------------
__global__ void tr_kernel()
{
    __shared__ unsigned short tile2[64][66];
    const int R = SS * K2H;
    const __nv_bfloat16* src = blockIdx.z ? g_f1tlo : g_f1thi;
    __nv_bfloat16*       dst = blockIdx.z ? g_f1lo  : g_f1hi;
    int i0 = blockIdx.x * 64;
    int tid = threadIdx.x;

#pragma unroll
    for (int ph = 0; ph < 8; ++ph) {
        int idx = ph * 256 + tid;
        int r  = idx >> 5;
        int cl = idx & 31;
        uint32_t w = *(const uint32_t*)(src + (size_t)(i0 + r) * 64 + cl * 2);
        tile2[cl * 2 + 0][r] = (unsigned short)(w & 0xffffu);
        tile2[cl * 2 + 1][r] = (unsigned short)(w >> 16);
    }
    __syncthreads();

#pragma unroll
    for (int ph = 0; ph < 8; ++ph) {
        int idx = ph * 256 + tid;
        int b  = idx >> 5;
        int cl = idx & 31;
        uint32_t w = *(const uint32_t*)&tile2[b][cl * 2];
        *(uint32_t*)(dst + (size_t)b * R + i0 + cl * 2) = w;
    }
}

// ---------------- launcher ----------------
extern "C" void kernel_launch(void* const* d_in, const int* in_sizes, int n_in,
                              void* d_out, int out_size)
{
    const float* f0     = (const float*)d_in[0];
    const int*   counts = (const int*)  d_in[1];
    const float* Wih_f  = (const float*)d_in[2];
    const float* Whh_f  = (const float*)d_in[3];
    const float* bih_f  = (const float*)d_in[4];
    const float* bhh_f  = (const float*)d_in[5];
    const float* Wih_b  = (const float*)d_in[6];
    const float* Whh_b  = (const float*)d_in[7];
    const float* bih_b  = (const float*)d_in[8];
    const float* bhh_b  = (const float*)d_in[9];
    const float* Wlin   = (const float*)d_in[10];
    const float* blin   = (const float*)d_in[11];
    float* out = (float*)d_out;

    void* p;
    cudaGetSymbolAddress(&p, g_xhi);     __nv_bfloat16* xhi = (__nv_bfloat16*)p;
    cudaGetSymbolAddress(&p, g_xlo);     __nv_bfloat16* xlo = (__nv_bfloat16*)p;
    cudaGetSymbolAddress(&p, g_xptf);    float* gxptf = (float*)p;
    cudaGetSymbolAddress(&p, g_xptb);    float* gxptb = (float*)p;
    cudaGetSymbolAddress(&p, g_f1hi);    __nv_bfloat16* f1hi = (__nv_bfloat16*)p;
    cudaGetSymbolAddress(&p, g_f1lo);    __nv_bfloat16* f1lo = (__nv_bfloat16*)p;
    cudaGetSymbolAddress(&p, g_wihf_hi); __nv_bfloat16* wfh = (__nv_bfloat16*)p;
    cudaGetSymbolAddress(&p, g_wihf_lo); __nv_bfloat16* wfl = (__nv_bfloat16*)p;
    cudaGetSymbolAddress(&p, g_wihb_hi); __nv_bfloat16* wbh = (__nv_bfloat16*)p;
    cudaGetSymbolAddress(&p, g_wihb_lo); __nv_bfloat16* wbl = (__nv_bfloat16*)p;
    cudaGetSymbolAddress(&p, g_wlin_hi); __nv_bfloat16* wlh = (__nv_bfloat16*)p;
    cudaGetSymbolAddress(&p, g_wlin_lo); __nv_bfloat16* wll = (__nv_bfloat16*)p;

    cudaFuncSetAttribute(lstm_kernel, cudaFuncAttributeMaxDynamicSharedMemorySize, LSMEM);
    cudaFuncSetAttribute(gemm3_kernel, cudaFuncAttributeMaxDynamicSharedMemorySize, 2 * STGB);

    int nw = FOURH * DD;
    int nl = CC * K2H;
    int ncvt = 2 * nw + nl;
    initcvt_kernel<<<(ncvt + 255) / 256, 256>>>(Wih_f, wfh, wfl, nw,
                                                Wih_b, wbh, wbl, nw,
                                                Wlin,  wlh, wll, nl);
    pool_kernel<<<BB, 256>>>(f0, counts, xhi, xlo);

    dim3 gproj(FOURH / 128, MM / 128);   // 12 x 256
    gemm3_kernel<<<gproj, 256, 2 * STGB>>>(xhi, xlo, wfh, wfl, bih_f, bhh_f,
                                           gxptf, FOURH, DD, 1);
    gemm3_kernel<<<gproj, 256, 2 * STGB>>>(xhi, xlo, wbh, wbl, bih_b, bhh_b,
                                           gxptb, FOURH, DD, 1);

    lstm_kernel<<<2 * NCD, RTH, LSMEM>>>(Whh_f, Whh_b);

    dim3 gtr(SS * K2H / 64, 1, 2);       // 6144 x 1 x 2
    tr_kernel<<<gtr, 256>>>();

    dim3 gout((CC + 127) / 128, MM / 128);  // 4 x 256
    gemm3_kernel<<<gout, 256, 2 * STGB>>>(f1hi, f1lo, wlh, wll, blin, nullptr,
                                          out, CC, K2H, 0);
}

// round 17
// speedup vs baseline: 2.1592x; 1.0707x over previous
#include <cuda_runtime.h>
#include <cuda_bf16.h>
#include <math.h>
#include <stdint.h>

// Problem dims
#define BB   64
#define SS   512
#define DD   768
#define WW   256
#define HH   384
#define FOURH 1536
#define CC   425
#define K2H  768
#define MM   (BB*SS)      // 32768 rows

// Recurrence config: 2 dirs x 4 batch-groups x 16 h-groups = 128 CTAs
#define NCD   64          // CTAs per direction
#define NBG   4           // batch groups (16 batches each)
#define CB    16          // batches per CTA
#define NJ    24          // h-indices per CTA
#define GR    96          // gate rows per CTA (4 gates * NJ)
#define RTH   384         // 12 warps, each owns one n8 tile of [16 x 96]

// -------- scratch (device globals; no allocation allowed) --------
__device__ __nv_bfloat16 g_xhi[MM * DD];
__device__ __nv_bfloat16 g_xlo[MM * DD];
__device__ float g_xptf[MM * FOURH];              // proj fwd, layout [t][feat][b]
__device__ float g_xptb[MM * FOURH];              // proj bwd, layout [t][feat][b]
__device__ __nv_bfloat16 g_f1thi[MM * K2H];       // [t][feat][b]
__device__ __nv_bfloat16 g_f1tlo[MM * K2H];
__device__ __nv_bfloat16 g_f1hi[MM * K2H];        // [b][t][feat] (post-transpose)
__device__ __nv_bfloat16 g_f1lo[MM * K2H];
__device__ __nv_bfloat16 g_hbhi[2][2][BB * HH];   // [dir][parity][b*384+k]
__device__ __nv_bfloat16 g_hblo[2][2][BB * HH];
__device__ unsigned g_bar[2][SS][NBG][2];         // per-step/bg/chunk counters (8 producers)
__device__ __nv_bfloat16 g_wihf_hi[FOURH * DD], g_wihf_lo[FOURH * DD];
__device__ __nv_bfloat16 g_wihb_hi[FOURH * DD], g_wihb_lo[FOURH * DD];
__device__ __nv_bfloat16 g_wlin_hi[CC * K2H],  g_wlin_lo[CC * K2H];

// ---------------- small helpers ----------------
__device__ __forceinline__ uint32_t smem_u32(const void* p) {
    uint32_t a;
    asm("{ .reg .u64 t; cvta.to.shared.u64 t, %1; cvt.u32.u64 %0, t; }"
        : "=r"(a) : "l"(p));
    return a;
}
__device__ __forceinline__ void cp16(uint32_t d, const void* s, bool v) {
    int sz = v ? 16 : 0;
    asm volatile("cp.async.cg.shared.global [%0], [%1], 16, %2;\n"
                 :: "r"(d), "l"(s), "r"(sz));
}
#define CP_COMMIT() asm volatile("cp.async.commit_group;\n")
#define CP_WAIT(n)  asm volatile("cp.async.wait_group %0;\n" :: "n"(n))

#define LDM4(r, addr) \
    asm volatile("ldmatrix.sync.aligned.m8n8.x4.shared.b16 {%0,%1,%2,%3}, [%4];" \
        : "=r"((r)[0]), "=r"((r)[1]), "=r"((r)[2]), "=r"((r)[3]) : "r"(addr))

#define MMA(d, a, b0, b1) \
    asm volatile("mma.sync.aligned.m16n8k16.row.col.f32.bf16.bf16.f32 " \
        "{%0,%1,%2,%3},{%4,%5,%6,%7},{%8,%9},{%0,%1,%2,%3};" \
        : "+f"((d)[0]), "+f"((d)[1]), "+f"((d)[2]), "+f"((d)[3]) \
        : "r"((a)[0]), "r"((a)[1]), "r"((a)[2]), "r"((a)[3]), "r"(b0), "r"(b1))

// release/acquire primitives for the dataflow counters
__device__ __forceinline__ unsigned ld_acq(const unsigned* p) {
    unsigned v;
    asm volatile("ld.acquire.gpu.global.u32 %0, [%1];" : "=r"(v) : "l"(p));
    return v;
}
__device__ __forceinline__ uint2 ld_acq2(const unsigned* p) {
    uint2 v;
    asm volatile("ld.acquire.gpu.global.v2.u32 {%0,%1}, [%2];"
        : "=r"(v.x), "=r"(v.y) : "l"(p));
    return v;
}
__device__ __forceinline__ void red_release(unsigned* p) {
    asm volatile("red.release.gpu.global.add.u32 [%0], 1;" :: "l"(p) : "memory");
}

// fast activations (clamped; rel err ~1e-6)
__device__ __forceinline__ float sigf(float x) {
    x = fminf(fmaxf(x, -30.0f), 30.0f);
    return __fdividef(1.0f, 1.0f + __expf(-x));
}
__device__ __forceinline__ float tanhfast(float x) {
    x = fminf(fmaxf(x, -15.0f), 15.0f);
    float e = __expf(2.0f * x);
    return __fdividef(e - 1.0f, e + 1.0f);
}

// ---------------- fused init (h state, counters) + weight hi/lo split ------
__global__ void initcvt_kernel(const float* __restrict__ in0, __nv_bfloat16* __restrict__ hi0,
                               __nv_bfloat16* __restrict__ lo0, int n0,
                               const float* __restrict__ in1, __nv_bfloat16* __restrict__ hi1,
                               __nv_bfloat16* __restrict__ lo1, int n1,
                               const float* __restrict__ in2, __nv_bfloat16* __restrict__ hi2,
                               __nv_bfloat16* __restrict__ lo2, int n2)
{
    int gid = blockIdx.x * blockDim.x + threadIdx.x;

    if (gid < 2 * BB * HH) {
        g_hbhi[gid / (BB * HH)][0][gid % (BB * HH)] = __float2bfloat16(0.0f);
        g_hblo[gid / (BB * HH)][0][gid % (BB * HH)] = __float2bfloat16(0.0f);
    }
    if (gid < 2 * SS * NBG * 2) (&g_bar[0][0][0][0])[gid] = 0u;

    int i = gid;
    const float* in; __nv_bfloat16 *hi, *lo;
    if (i < n0)                { in = in0; hi = hi0; lo = lo0; }
    else if (i < n0 + n1)      { i -= n0; in = in1; hi = hi1; lo = lo1; }
    else if (i < n0 + n1 + n2) { i -= n0 + n1; in = in2; hi = hi2; lo = lo2; }
    else return;
    float v = in[i];
    __nv_bfloat16 h = __float2bfloat16(v);
    hi[i] = h;
    lo[i] = __float2bfloat16(v - __bfloat162float(h));
}

// ---------------- segment mean pool (writes split bf16) ----------------
__global__ void pool_kernel(const float* __restrict__ f0,
                            const int*   __restrict__ counts,
                            __nv_bfloat16* __restrict__ xhi,
                            __nv_bfloat16* __restrict__ xlo)
{
    __shared__ int s_start[WW];
    __shared__ int s_cnt[WW];
    int b = blockIdx.x;
    int tid = threadIdx.x;
    if (tid == 0) {
        int run = 0;
        for (int j = 0; j < WW; ++j) {
            int c = counts[b * WW + j];
            s_start[j] = run; s_cnt[j] = c; run += c;
        }
    }
    __syncthreads();
    const float* fb = f0 + (size_t)b * SS * DD;
    __nv_bfloat16* xh = xhi + (size_t)b * SS * DD;
    __nv_bfloat16* xl = xlo + (size_t)b * SS * DD;
    for (int idx = tid; idx < WW * DD; idx += blockDim.x) {
        int j = idx / DD, d = idx - j * DD;
        int st = s_start[j], c = s_cnt[j];
        float v = 0.0f;
        for (int p = 0; p < c; ++p) v += fb[(size_t)(st + p) * DD + d];
        v /= (float)c;
        __nv_bfloat16 h = __float2bfloat16(v);
        xh[idx] = h;
        xl[idx] = __float2bfloat16(v - __bfloat162float(h));
    }
    for (int idx = tid; idx < (SS - WW) * DD; idx += blockDim.x) {
        float v = fb[WW * DD + idx];
        __nv_bfloat16 h = __float2bfloat16(v);
        xh[WW * DD + idx] = h;
        xl[WW * DD + idx] = __float2bfloat16(v - __bfloat162float(h));
    }
}

// ---------------- split-bf16 tensor-core GEMM (mma.sync) ----------------
// Unchanged (683us/launch, tensor 55.8%, occ 24.4%).
#define ARRB  (128 * 80)
#define STGB  (4 * ARRB)

__global__ void __launch_bounds__(256, 2)
gemm3_kernel(const __nv_bfloat16* __restrict__ Ahi, const __nv_bfloat16* __restrict__ Alo,
             const __nv_bfloat16* __restrict__ Bhi, const __nv_bfloat16* __restrict__ Blo,
             const float* __restrict__ bias1, const float* __restrict__ bias2,
             float* __restrict__ C, int N, int K, int tstore)
{
    extern __shared__ char smem[];
    uint32_t sb = smem_u32(smem);
    int tid = threadIdx.x, lane = tid & 31, wid = tid >> 5;
    int wm = wid >> 2, wn = wid & 3;
    int bm = blockIdx.y, bn = blockIdx.x;

    int lr = tid >> 1;
    int lc = (tid & 1) * 2;
    int arow = tstore ? ((lr & 63) * SS + bm * 2 + (lr >> 6))
                      : (bm * 128 + lr);
    int brow = bn * 128 + lr;
    bool bv  = brow < N;
    const __nv_bfloat16* pAh = Ahi + (size_t)arow * K;
    const __nv_bfloat16* pAl = Alo + (size_t)arow * K;
    const __nv_bfloat16* pBh = Bhi + (size_t)(bv ? brow : 0) * K;
    const __nv_bfloat16* pBl = Blo + (size_t)(bv ? brow : 0) * K;
    uint32_t sd = sb + lr * 80 + lc * 16;

    float acc[4][4][4];
#pragma unroll
    for (int a = 0; a < 4; ++a)
#pragma unroll
        for (int b = 0; b < 4; ++b)
#pragma unroll
            for (int c = 0; c < 4; ++c) acc[a][b][c] = 0.0f;

    int KT = K >> 5;

    {
        uint32_t d = sd;
#pragma unroll
        for (int cc = 0; cc < 2; ++cc) {
            cp16(d + cc * 16 + 0 * ARRB, pAh + (lc + cc) * 8, true);
            cp16(d + cc * 16 + 1 * ARRB, pAl + (lc + cc) * 8, true);
            cp16(d + cc * 16 + 2 * ARRB, pBh + (lc + cc) * 8, bv);
            cp16(d + cc * 16 + 3 * ARRB, pBl + (lc + cc) * 8, bv);
        }
        CP_COMMIT();
    }

    int la  = lane & 15, lc4 = lane >> 4;
    int lb  = (lane & 7) + ((lane & 16) >> 1);
    int lbc = (lane >> 3) & 1;

    for (int i = 0; i < KT; ++i) {
        CP_WAIT(0);
        __syncthreads();
        if (i + 1 < KT) {
            int ko = (i + 1) << 5;
            uint32_t d = sd + ((i + 1) & 1) * STGB;
#pragma unroll
            for (int cc = 0; cc < 2; ++cc) {
                cp16(d + cc * 16 + 0 * ARRB, pAh + ko + (lc + cc) * 8, true);
                cp16(d + cc * 16 + 1 * ARRB, pAl + ko + (lc + cc) * 8, true);
                cp16(d + cc * 16 + 2 * ARRB, pBh + ko + (lc + cc) * 8, bv);
                cp16(d + cc * 16 + 3 * ARRB, pBl + ko + (lc + cc) * 8, bv);
            }
            CP_COMMIT();
        }
        uint32_t st = sb + (i & 1) * STGB;
#pragma unroll
        for (int kh = 0; kh < 2; ++kh) {
            uint32_t aaddr = st + (wm * 64 + la) * 80 + (kh * 2 + lc4) * 16;
            uint32_t ah[4][4], al[4][4];
#pragma unroll
            for (int mt = 0; mt < 4; ++mt) {
                LDM4(ah[mt], aaddr + mt * 1280);
                LDM4(al[mt], aaddr + mt * 1280 + ARRB);
            }
            uint32_t bbase = st + 2 * ARRB + (wn * 32 + lb) * 80 + (kh * 2 + lbc) * 16;
            uint32_t bh[2][4], bl[2][4];
#pragma unroll
            for (int ntp = 0; ntp < 2; ++ntp) {
                LDM4(bh[ntp], bbase + ntp * 1280);
                LDM4(bl[ntp], bbase + ntp * 1280 + ARRB);
            }
#pragma unroll
            for (int mt = 0; mt < 4; ++mt)
#pragma unroll
                for (int ntp = 0; ntp < 2; ++ntp) {
                    MMA(acc[mt][2 * ntp + 0], ah[mt], bh[ntp][0], bh[ntp][1]);
                    MMA(acc[mt][2 * ntp + 1], ah[mt], bh[ntp][2], bh[ntp][3]);
                }
#pragma unroll
            for (int mt = 0; mt < 4; ++mt)
#pragma unroll
                for (int ntp = 0; ntp < 2; ++ntp) {
                    MMA(acc[mt][2 * ntp + 0], ah[mt], bl[ntp][0], bl[ntp][1]);
                    MMA(acc[mt][2 * ntp + 1], ah[mt], bl[ntp][2], bl[ntp][3]);
                }
#pragma unroll
            for (int mt = 0; mt < 4; ++mt)
#pragma unroll
                for (int ntp = 0; ntp < 2; ++ntp) {
                    MMA(acc[mt][2 * ntp + 0], al[mt], bh[ntp][0], bh[ntp][1]);
                    MMA(acc[mt][2 * ntp + 1], al[mt], bh[ntp][2], bh[ntp][3]);
                }
        }
        __syncthreads();
    }

    // epilogue
#pragma unroll
    for (int mt = 0; mt < 4; ++mt) {
        int r0_ = wm * 64 + mt * 16 + (lane >> 2);      // tile row 0..127
#pragma unroll
        for (int nt = 0; nt < 4; ++nt) {
            int n0 = bn * 128 + wn * 32 + nt * 8 + (lane & 3) * 2;
            float* a = acc[mt][nt];
            if (!tstore) {
                int m0 = bm * 128 + r0_;
                if (n0 < N) {
                    float bs = bias1[n0] + (bias2 ? bias2[n0] : 0.0f);
                    C[(size_t)m0 * N + n0]       = a[0] + bs;
                    C[(size_t)(m0 + 8) * N + n0] = a[2] + bs;
                }
                if (n0 + 1 < N) {
                    float bs = bias1[n0 + 1] + (bias2 ? bias2[n0 + 1] : 0.0f);
                    C[(size_t)m0 * N + n0 + 1]       = a[1] + bs;
                    C[(size_t)(m0 + 8) * N + n0 + 1] = a[3] + bs;
                }
            } else {
                int b_ = r0_ & 63;
                int t_ = bm * 2 + (r0_ >> 6);
                float bs0 = bias1[n0] + bias2[n0];
                float bs1 = bias1[n0 + 1] + bias2[n0 + 1];
                size_t o0 = ((size_t)t_ * N + n0) * 64 + b_;
                C[o0]          = a[0] + bs0;
                C[o0 + 64]     = a[1] + bs1;
                C[o0 + 8]      = a[2] + bs0;
                C[o0 + 64 + 8] = a[3] + bs1;
            }
        }
    }
}

// ---------------- persistent tensor-core LSTM recurrence (2-D partition) ---
// CTA (dir, bg, hg): gates [16 batches x 96 rows] from h[16 batches x 384].
// h copy: 24KB/step in TWO 12KB chunks. Counter per (dir,step,bg,chunk):
// producers = 8 CTAs (hg>>3), consumers = same-bg CTAs.
#define PITCH   784
#define LA_HI   0                         // 16 rows * 784
#define LA_LO   12544
#define LW_HI   25088                     // 96 rows * 784
#define LW_LO   100352
#define LGATES  175616                    // 16 * 98 floats
#define LCS     181888                    // 384 floats
#define LHSTH   183424                    // 384 bf16
#define LHSTL   184192
#define LSMEM   184960
#define GPITCH  98

__global__ void __launch_bounds__(RTH, 1)
lstm_kernel(const float* __restrict__ Whh_f, const float* __restrict__ Whh_b)
{
    extern __shared__ char smem[];
    uint32_t sb = smem_u32(smem);
    float* gates_s = (float*)(smem + LGATES);
    float* c_s     = (float*)(smem + LCS);

    int cta = blockIdx.x;
    int dir = (cta >= NCD) ? 1 : 0;
    int ci  = cta - dir * NCD;
    int bg  = ci >> 4;                 // 0..3  batch group
    int hg  = ci & 15;                 // 0..15 h group
    const float* Whh = dir ? Whh_b : Whh_f;
    const float* xp  = dir ? g_xptb : g_xptf;
    int tid = threadIdx.x;
    int lane = tid & 31, wid = tid >> 5;
    int nt = wid;                      // each warp owns one n8 tile of 96 rows

    // ---- load + split Whh slice (96 rows x 384) into SMEM (once) ----
    for (int idx = tid; idx < GR * HH; idx += RTH) {
        int r = idx / HH, k = idx - r * HH;
        int gi = r / NJ, lj = r - gi * NJ;
        float v = Whh[(size_t)(gi * HH + hg * NJ + lj) * HH + k];
        __nv_bfloat16 h = __float2bfloat16(v);
        *(__nv_bfloat16*)(smem + LW_HI + r * PITCH + k * 2) = h;
        *(__nv_bfloat16*)(smem + LW_LO + r * PITCH + k * 2) =
            __float2bfloat16(v - __bfloat162float(h));
    }
    c_s[tid] = 0.0f;
    __syncthreads();

    // cell mapping: thread -> (batch b, local h-index lj)
    int cb_ = tid & 15;                // 0..15
    int lj  = tid >> 4;                // 0..23

    // ldmatrix addresses
    int la  = lane & 15, lc4 = lane >> 4;
    uint32_t aAddrBase = sb + LA_HI + la * PITCH + lc4 * 16;
    uint32_t bAddrBase = sb + LW_HI + ((lane >= 16) ? (LW_LO - LW_HI) : 0u)
                       + (nt * 8 + (lane & 7)) * PITCH + ((lane >> 3) & 1) * 16;

    // copy mapping: thread -> (comp hi/lo, then 2 x (row, 16B chunk))
    int ccomp = tid / 192;
    int crr   = tid - ccomp * 192;

    // xp prefetch (transposed [t][feat][b]; feat = gi*384 + hg*24 + lj)
    float xg[4];
    {
        int t0 = dir ? (SS - 1) : 0;
        const float* xr = xp + ((size_t)t0 * FOURH + hg * NJ + lj) * 64 + bg * CB + cb_;
#pragma unroll
        for (int gi = 0; gi < 4; ++gi) xg[gi] = __ldg(xr + (size_t)gi * HH * 64);
    }

    for (int s = 0; s < SS; ++s) {
        int t = dir ? (SS - 1 - s) : s;
        int p = s & 1;
        int np = (s + 1) & 1;

        const char* srcH = (const char*)&g_hbhi[dir][p][0] + bg * CB * HH * 2;
        const char* srcL = (const char*)&g_hblo[dir][p][0] + bg * CB * HH * 2;
        const char* csrc = ccomp ? srcL : srcH;
        uint32_t cbase = sb + (ccomp ? LA_LO : LA_HI);

        // chunk readiness: counter[dir][s-1][bg][q] reaches 8
        uint2 cnt = make_uint2(8u, 8u);
        if (s > 0) cnt = ld_acq2(&g_bar[dir][s - 1][bg][0]);

#pragma unroll
        for (int q = 0; q < 2; ++q) {
            unsigned have = q ? cnt.y : cnt.x;
            if (have < 8u) {
                const unsigned* cp_ = &g_bar[dir][s - 1][bg][q];
                do { have = ld_acq(cp_); } while (have < 8u);
            }
            // copy chunk q: k-bytes [384q, 384q+384) of 16 rows (one comp)
#pragma unroll
            for (int i = 0; i < 2; ++i) {
                int e = i * 192 + crr;            // 0..383
                int row = e / 24, cc = e - row * 24;
                cp16(cbase + row * PITCH + q * 384 + cc * 16,
                     csrc + row * 768 + q * 384 + cc * 16, true);
            }
            CP_COMMIT();
        }

        // gate GEMM: 24 k16 steps in 2 chunks
        float acc[4] = {0.f, 0.f, 0.f, 0.f};
#pragma unroll
        for (int q = 0; q < 2; ++q) {
            if (q == 0) CP_WAIT(1); else CP_WAIT(0);
            __syncthreads();
#pragma unroll
            for (int kk = 0; kk < 12; ++kk) {
                int k16 = q * 12 + kk;
                uint32_t ka = aAddrBase + k16 * 32;
                uint32_t kb = bAddrBase + k16 * 32;
                uint32_t ah[4], al[4], bb[4];
                LDM4(ah, ka);
                LDM4(al, ka + (LA_LO - LA_HI));
                LDM4(bb, kb);                      // {bh0, bh1, bl0, bl1}
                MMA(acc, ah, bb[0], bb[1]);
                MMA(acc, ah, bb[2], bb[3]);
                MMA(acc, al, bb[0], bb[1]);
            }
        }

        // epilogue: gates [b][r], pitch 98 floats
        {
            int brow = lane >> 2;
            int rcol = nt * 8 + (lane & 3) * 2;
            *(float2*)&gates_s[brow * GPITCH + rcol]       = make_float2(acc[0], acc[1]);
            *(float2*)&gates_s[(brow + 8) * GPITCH + rcol] = make_float2(acc[2], acc[3]);
        }
        __syncthreads();

        // cell update (1 cell per thread: batch cb_, local h lj)
        {
            float ig = gates_s[cb_ * GPITCH + 0 * NJ + lj] + xg[0];
            float fg = gates_s[cb_ * GPITCH + 1 * NJ + lj] + xg[1];
            float gg = gates_s[cb_ * GPITCH + 2 * NJ + lj] + xg[2];
            float og = gates_s[cb_ * GPITCH + 3 * NJ + lj] + xg[3];
            float c  = c_s[tid];
            c = sigf(fg) * c + sigf(ig) * tanhfast(gg);
            float h = sigf(og) * tanhfast(c);
            c_s[tid] = c;
            __nv_bfloat16 hh = __float2bfloat16(h);
            __nv_bfloat16 hl = __float2bfloat16(h - __bfloat162float(hh));
            ((__nv_bfloat16*)(smem + LHSTH))[cb_ * NJ + lj] = hh;
            ((__nv_bfloat16*)(smem + LHSTL))[cb_ * NJ + lj] = hl;
            size_t fo = ((size_t)t * K2H + dir * HH + hg * NJ + lj) * 64 + bg * CB + cb_;
            g_f1thi[fo] = hh;
            g_f1tlo[fo] = hl;
        }

        // prefetch xp for next step
        if (s + 1 < SS) {
            int t1 = dir ? (SS - 2 - s) : (s + 1);
            const float* xr = xp + ((size_t)t1 * FOURH + hg * NJ + lj) * 64 + bg * CB + cb_;
#pragma unroll
            for (int gi = 0; gi < 4; ++gi) xg[gi] = __ldg(xr + (size_t)gi * HH * 64);
        }

        __syncthreads();   // h stage visible

        // cooperative h write: 48B (12 u32) per (comp, batch)
        {
            int comp = tid / 192;
            int rr   = tid - comp * 192;
            int b    = rr / 12;
            int w    = rr - b * 12;
            const uint32_t* ssrc = (const uint32_t*)(smem + (comp ? LHSTL : LHSTH) + b * NJ * 2);
            __nv_bfloat16* gdst = (comp ? &g_hblo[dir][np][0] : &g_hbhi[dir][np][0])
                                  + (bg * CB + b) * HH + hg * NJ;
            ((uint32_t*)gdst)[w] = ssrc[w];
        }

        // arrive: release-add on this CTA's (bg, chunk) counter
        __syncthreads();
        if (tid == 0) red_release(&g_bar[dir][s][bg][hg >> 3]);
    }
}

// ---------------- f1t [t][feat][b] -> f1 [b][t][feat] transpose ----------------
__global__ void tr_kernel()
{
    __shared__ unsigned short tile2[64][66];
    const int R = SS * K2H;
    const __nv_bfloat16* src = blockIdx.z ? g_f1tlo : g_f1thi;
    __nv_bfloat16*       dst = blockIdx.z ? g_f1lo  : g_f1hi;
    int i0 = blockIdx.x * 64;
    int tid = threadIdx.x;

#pragma unroll
    for (int ph = 0; ph < 8; ++ph) {
        int idx = ph * 256 + tid;
        int r  = idx >> 5;
        int cl = idx & 31;
        uint32_t w = *(const uint32_t*)(src + (size_t)(i0 + r) * 64 + cl * 2);
        tile2[cl * 2 + 0][r] = (unsigned short)(w & 0xffffu);
        tile2[cl * 2 + 1][r] = (unsigned short)(w >> 16);
    }
    __syncthreads();

#pragma unroll
    for (int ph = 0; ph < 8; ++ph) {
        int idx = ph * 256 + tid;
        int b  = idx >> 5;
        int cl = idx & 31;
        uint32_t w = *(const uint32_t*)&tile2[b][cl * 2];
        *(uint32_t*)(dst + (size_t)b * R + i0 + cl * 2) = w;
    }
}

// ---------------- launcher ----------------
extern "C" void kernel_launch(void* const* d_in, const int* in_sizes, int n_in,
                              void* d_out, int out_size)
{
    const float* f0     = (const float*)d_in[0];
    const int*   counts = (const int*)  d_in[1];
    const float* Wih_f  = (const float*)d_in[2];
    const float* Whh_f  = (const float*)d_in[3];
    const float* bih_f  = (const float*)d_in[4];
    const float* bhh_f  = (const float*)d_in[5];
    const float* Wih_b  = (const float*)d_in[6];
    const float* Whh_b  = (const float*)d_in[7];
    const float* bih_b  = (const float*)d_in[8];
    const float* bhh_b  = (const float*)d_in[9];
    const float* Wlin   = (const float*)d_in[10];
    const float* blin   = (const float*)d_in[11];
    float* out = (float*)d_out;

    void* p;
    cudaGetSymbolAddress(&p, g_xhi);     __nv_bfloat16* xhi = (__nv_bfloat16*)p;
    cudaGetSymbolAddress(&p, g_xlo);     __nv_bfloat16* xlo = (__nv_bfloat16*)p;
    cudaGetSymbolAddress(&p, g_xptf);    float* gxptf = (float*)p;
    cudaGetSymbolAddress(&p, g_xptb);    float* gxptb = (float*)p;
    cudaGetSymbolAddress(&p, g_f1hi);    __nv_bfloat16* f1hi = (__nv_bfloat16*)p;
    cudaGetSymbolAddress(&p, g_f1lo);    __nv_bfloat16* f1lo = (__nv_bfloat16*)p;
    cudaGetSymbolAddress(&p, g_wihf_hi); __nv_bfloat16* wfh = (__nv_bfloat16*)p;
    cudaGetSymbolAddress(&p, g_wihf_lo); __nv_bfloat16* wfl = (__nv_bfloat16*)p;
    cudaGetSymbolAddress(&p, g_wihb_hi); __nv_bfloat16* wbh = (__nv_bfloat16*)p;
    cudaGetSymbolAddress(&p, g_wihb_lo); __nv_bfloat16* wbl = (__nv_bfloat16*)p;
    cudaGetSymbolAddress(&p, g_wlin_hi); __nv_bfloat16* wlh = (__nv_bfloat16*)p;
    cudaGetSymbolAddress(&p, g_wlin_lo); __nv_bfloat16* wll = (__nv_bfloat16*)p;

    cudaFuncSetAttribute(lstm_kernel, cudaFuncAttributeMaxDynamicSharedMemorySize, LSMEM);
    cudaFuncSetAttribute(gemm3_kernel, cudaFuncAttributeMaxDynamicSharedMemorySize, 2 * STGB);

    int nw = FOURH * DD;
    int nl = CC * K2H;
    int ncvt = 2 * nw + nl;
    initcvt_kernel<<<(ncvt + 255) / 256, 256>>>(Wih_f, wfh, wfl, nw,
                                                Wih_b, wbh, wbl, nw,
                                                Wlin,  wlh, wll, nl);
    pool_kernel<<<BB, 256>>>(f0, counts, xhi, xlo);

    dim3 gproj(FOURH / 128, MM / 128);   // 12 x 256
    gemm3_kernel<<<gproj, 256, 2 * STGB>>>(xhi, xlo, wfh, wfl, bih_f, bhh_f,
                                           gxptf, FOURH, DD, 1);
    gemm3_kernel<<<gproj, 256, 2 * STGB>>>(xhi, xlo, wbh, wbl, bih_b, bhh_b,
                                           gxptb, FOURH, DD, 1);

    lstm_kernel<<<2 * NCD, RTH, LSMEM>>>(Whh_f, Whh_b);

    dim3 gtr(SS * K2H / 64, 1, 2);       // 6144 x 1 x 2
    tr_kernel<<<gtr, 256>>>();

    dim3 gout((CC + 127) / 128, MM / 128);  // 4 x 256
    gemm3_kernel<<<gout, 256, 2 * STGB>>>(f1hi, f1lo, wlh, wll, blin, nullptr,
                                          out, CC, K2H, 0);
}